// round 2
// baseline (speedup 1.0000x reference)
#include <cuda_runtime.h>
#include <cuda_bf16.h>
#include <math.h>

// ---------------- problem constants ----------------
#define SEQLEN   8192        // L
#define HD       768         // hidden dim D
#define NB       8           // batch
#define FO       64          // filter order
#define N2       8192        // half FFT size (complex FFT length)
#define NFFT     16384       // real FFT size (2L)
#define NT       1024        // threads per FFT block

// ---------------- device scratch (static allocation allowed) ----------------
__device__ float  g_h  [SEQLEN * FO];                 // MLP output h (L, 64)
__device__ float  g_kT [HD * SEQLEN];                 // filter k transposed (D, L)
__device__ float2 g_Kf [HD * (N2 + 1)];               // filter spectrum / NFFT
__device__ float  g_xT [(size_t)NB * HD * SEQLEN];    // x transposed; y written in-place
__device__ float2 g_tw [N2];                          // twiddle tables (per-stage contiguous)

// ============================================================================
// Twiddle tables: stage with half-size m at offset 8192-2m, entries
// e^{-i*pi*p/m}, p<m.  Filled once in gmem, copied to smem per FFT CTA.
// ============================================================================
__global__ void twfill_kernel() {
    int off = 0;
    for (int m = 4096; m >= 1; m >>= 1) {
        for (int p = threadIdx.x; p < m; p += 1024) {
            float s, c;
            sincospif(-(float)p / (float)m, &s, &c);
            g_tw[off + p] = make_float2(c, s);
        }
        off += m;
    }
    if (threadIdx.x == 0) g_tw[8191] = make_float2(1.f, 0.f);
}

// ============================================================================
// Kernel A: implicit filter MLP  (per position l: 3 -> 64 -> 64 -> 64, sin)
// ============================================================================
__global__ void mlp_kernel(const float* __restrict__ w_in, const float* __restrict__ b_in,
                           const float* __restrict__ freq_in,
                           const float* __restrict__ w_h0, const float* __restrict__ b_h0,
                           const float* __restrict__ freq_h0,
                           const float* __restrict__ w_h1, const float* __restrict__ b_h1,
                           const float* __restrict__ freq_h1) {
    __shared__ float hs[FO];
    int l = blockIdx.x;
    int j = threadIdx.x;

    float t   = (float)l * (1.0f / (float)(SEQLEN - 1));
    float wan = 6.283185307179586f * (float)l / (float)SEQLEN;
    float ph  = 1e-4f * wan;
    float z0 = t, z1 = cosf(ph), z2 = -sinf(ph);

    float a = fmaf(z0, w_in[j], fmaf(z1, w_in[FO + j], fmaf(z2, w_in[2 * FO + j], b_in[j])));
    hs[j] = sinf(freq_in[j] * a);
    __syncthreads();

    float acc = b_h0[j];
#pragma unroll
    for (int i = 0; i < FO; i++) acc = fmaf(hs[i], w_h0[i * FO + j], acc);
    float v = sinf(freq_h0[j] * acc);
    __syncthreads();
    hs[j] = v;
    __syncthreads();

    acc = b_h1[j];
#pragma unroll
    for (int i = 0; i < FO; i++) acc = fmaf(hs[i], w_h1[i * FO + j], acc);
    g_h[l * FO + j] = sinf(freq_h1[j] * acc);
}

// ============================================================================
// Kernel B: k^T[d][l] = (h[l] . w_out[:,d]) * exp(-t*|delta_d|)
// ============================================================================
__global__ void kgemm_kernel(const float* __restrict__ w_out) {
    __shared__ float hs[128][FO];
    __shared__ float ws[FO][32];
    int l0 = blockIdx.x * 128;
    int d0 = blockIdx.y * 32;
    int tid = threadIdx.x;   // 256

    for (int idx = tid; idx < 128 * FO; idx += 256)
        hs[idx >> 6][idx & 63] = g_h[(l0 + (idx >> 6)) * FO + (idx & 63)];
    for (int idx = tid; idx < FO * 32; idx += 256)
        ws[idx >> 5][idx & 31] = w_out[(idx >> 5) * HD + d0 + (idx & 31)];
    __syncthreads();

    int dx = tid & 31, ly = tid >> 5;
    int d = d0 + dx;
    const float ln001 = -4.605170185988091f;   // ln(0.01)
    float mind = ln001 / 1.5f, maxd = ln001 / 0.3f;
    float delta = mind + (maxd - mind) * ((float)d / (float)(HD - 1));
    float ad = fabsf(delta);

    for (int ls = ly; ls < 128; ls += 8) {
        float acc = 0.f;
#pragma unroll
        for (int i = 0; i < FO; i++) acc = fmaf(hs[ls][i], ws[i][dx], acc);
        int l = l0 + ls;
        float t = (float)l * (1.0f / (float)(SEQLEN - 1));
        g_kT[(size_t)d * SEQLEN + l] = acc * expf(-t * ad);
    }
}

// ============================================================================
// Shared-memory FFT machinery (N2 = 8192 complex, NT threads).
// Forward: DIF (natural -> bit reversed).  Inverse: DIT (bit rev -> natural).
// ============================================================================
__device__ __forceinline__ void load_tw(float2* tw) {
    const float4* src = (const float4*)g_tw;
    float4* dst = (float4*)tw;
#pragma unroll
    for (int it = 0; it < 4096 / NT; it++)
        dst[threadIdx.x + it * NT] = src[threadIdx.x + it * NT];
}

// forward stages m = 2048 .. 1 (stage m=4096 fused with the load)
__device__ __forceinline__ void fft_fwd_stages(float2* Z, const float2* tw) {
    int off = 4096;
    for (int m = 2048; m >= 1; m >>= 1) {
        __syncthreads();
#pragma unroll
        for (int it = 0; it < N2 / 2 / NT; it++) {
            int i = threadIdx.x + it * NT;
            int p = i & (m - 1);
            int a = 2 * i - p;
            float2 za = Z[a], zb = Z[a + m];
            float2 w = tw[off + p];
            Z[a] = make_float2(za.x + zb.x, za.y + zb.y);
            float tx = za.x - zb.x, ty = za.y - zb.y;
            Z[a + m] = make_float2(tx * w.x - ty * w.y, tx * w.y + ty * w.x);
        }
        off += m;
    }
    __syncthreads();
}

// inverse stages m = 1 .. 2048 (final stage m=4096 fused with the store)
__device__ __forceinline__ void fft_inv_stages(float2* Z, const float2* tw) {
    for (int m = 1; m <= 2048; m <<= 1) {
        int off = 8192 - 2 * m;
        __syncthreads();
#pragma unroll
        for (int it = 0; it < N2 / 2 / NT; it++) {
            int i = threadIdx.x + it * NT;
            int p = i & (m - 1);
            int a = 2 * i - p;
            float2 w = tw[off + p];              // conj applied inline
            float2 zb = Z[a + m];
            float tx = zb.x * w.x + zb.y * w.y;
            float ty = zb.y * w.x - zb.x * w.y;
            float2 za = Z[a];
            Z[a]     = make_float2(za.x + tx, za.y + ty);
            Z[a + m] = make_float2(za.x - tx, za.y - ty);
        }
    }
    __syncthreads();
}

__device__ __forceinline__ int brev13(int k) {
    return (int)(__brev((unsigned)k) >> 19);
}

// ============================================================================
// Kernel C: filter spectrum.  One CTA per d.
//   Kf[d][k] = rfft(k_d zero-padded to 16384)[k] / 16384 ,  k = 0..8192
// ============================================================================
__global__ void __launch_bounds__(NT) kfft_kernel() {
    extern __shared__ float2 smem2[];
    float2* tw = smem2;            // 8192 float2
    float2* Z  = smem2 + 8192;     // 8192 float2
    int d = blockIdx.x, tid = threadIdx.x;

    load_tw(tw);
    __syncthreads();

    // fused load + first DIF stage (upper half of z is zero)
    const float2* krow = (const float2*)(g_kT + (size_t)d * SEQLEN);
#pragma unroll
    for (int it = 0; it < 4096 / NT; it++) {
        int i = tid + it * NT;
        float2 v = krow[i];
        Z[i] = v;
        float2 w = tw[i];          // stage m=4096 table at offset 0
        Z[i + 4096] = make_float2(v.x * w.x - v.y * w.y, v.x * w.y + v.y * w.x);
    }
    fft_fwd_stages(Z, tw);

    const float invN = 1.0f / (float)NFFT;
    float2* out = g_Kf + (size_t)d * (N2 + 1);
    for (int k = tid; k <= 4096; k += NT) {
        if (k == 0) {
            float2 A = Z[0];
            out[0]    = make_float2((A.x + A.y) * invN, 0.f);
            out[8192] = make_float2((A.x - A.y) * invN, 0.f);
        } else {
            int j = 8192 - k;
            float2 A  = Z[brev13(k)];
            float2 Bv = Z[brev13(j)];
            float2 Fe = make_float2(0.5f * (A.x + Bv.x), 0.5f * (A.y - Bv.y));
            float dx = A.x - Bv.x, dy = A.y + Bv.y;
            float2 Fo = make_float2(0.5f * dy, -0.5f * dx);
            float s, c;
            sincospif(-(float)k * (1.0f / 8192.0f), &s, &c);     // e^{-2*pi*i*k/16384}
            float2 WFo = make_float2(c * Fo.x - s * Fo.y, c * Fo.y + s * Fo.x);
            out[k] = make_float2((Fe.x + WFo.x) * invN,  (Fe.y + WFo.y) * invN);
            out[j] = make_float2((Fe.x - WFo.x) * invN, -(Fe.y - WFo.y) * invN);
        }
    }
}

// ============================================================================
// Transposes:  x (B,L,D) -> xT (B,D,L)   and   xT (holding y) -> out (B,L,D)
// ============================================================================
__global__ void transpose_in(const float* __restrict__ x) {
    __shared__ float tile[32][33];
    int b = blockIdx.z;
    int l0 = blockIdx.x << 5, d0 = blockIdx.y << 5;
    int tx = threadIdx.x, ty = threadIdx.y;
#pragma unroll
    for (int r = 0; r < 4; r++) {
        int l = l0 + ty + r * 8;
        tile[ty + r * 8][tx] = x[((size_t)b * SEQLEN + l) * HD + d0 + tx];
    }
    __syncthreads();
#pragma unroll
    for (int r = 0; r < 4; r++) {
        int d = d0 + ty + r * 8;
        g_xT[((size_t)b * HD + d) * SEQLEN + l0 + tx] = tile[tx][ty + r * 8];
    }
}

__global__ void transpose_out(float* __restrict__ out) {
    __shared__ float tile[32][33];
    int b = blockIdx.z;
    int l0 = blockIdx.x << 5, d0 = blockIdx.y << 5;
    int tx = threadIdx.x, ty = threadIdx.y;
#pragma unroll
    for (int r = 0; r < 4; r++) {
        int d = d0 + ty + r * 8;
        tile[ty + r * 8][tx] = g_xT[((size_t)b * HD + d) * SEQLEN + l0 + tx];
    }
    __syncthreads();
#pragma unroll
    for (int r = 0; r < 4; r++) {
        int l = l0 + ty + r * 8;
        out[((size_t)b * SEQLEN + l) * HD + d0 + tx] = tile[tx][ty + r * 8];
    }
}

// ============================================================================
// Kernel D: per-channel FFT convolution.  One CTA per (b,d).
//   rfft16384 via packed 8192-pt complex DIF, pointwise *Kf in bit-reversed
//   order, irfft via DIT, +bias.  Writes y in-place over its xT row.
// ============================================================================
__global__ void __launch_bounds__(NT) fftconv_kernel(const float* __restrict__ bias) {
    extern __shared__ float2 smem2[];
    float2* tw = smem2;
    float2* Z  = smem2 + 8192;
    int bd = blockIdx.x, tid = threadIdx.x;
    int d = bd % HD;

    load_tw(tw);
    __syncthreads();

    // fused load + first DIF stage (upper half of z is zero)
    float2* xrow = (float2*)(g_xT + (size_t)bd * SEQLEN);
#pragma unroll
    for (int it = 0; it < 4096 / NT; it++) {
        int i = tid + it * NT;
        float2 v = xrow[i];
        Z[i] = v;
        float2 w = tw[i];
        Z[i + 4096] = make_float2(v.x * w.x - v.y * w.y, v.x * w.y + v.y * w.x);
    }
    fft_fwd_stages(Z, tw);

    // unpack -> X[k], multiply by Kf, repack (all in bit-reversed slots)
    const float2* Kf = g_Kf + (size_t)d * (N2 + 1);
    for (int k = tid; k <= 4096; k += NT) {
        if (k == 0) {
            float2 A = Z[0];
            float X0 = A.x + A.y, XN = A.x - A.y;
            float2 K0 = Kf[0], KN = Kf[8192];
            float2 Y0 = make_float2(X0 * K0.x, X0 * K0.y);
            float2 YN = make_float2(XN * KN.x, XN * KN.y);
            float2 Ge = make_float2(0.5f * (Y0.x + YN.x), 0.5f * (Y0.y - YN.y));
            float2 Go = make_float2(0.5f * (Y0.x - YN.x), 0.5f * (Y0.y + YN.y));
            Z[0] = make_float2(Ge.x - Go.y, Ge.y + Go.x);
        } else {
            int j = 8192 - k;
            int ra = brev13(k), rb = brev13(j);
            float2 A  = Z[ra];
            float2 Bv = Z[rb];
            float2 Fe = make_float2(0.5f * (A.x + Bv.x), 0.5f * (A.y - Bv.y));
            float dx = A.x - Bv.x, dy = A.y + Bv.y;
            float2 Fo = make_float2(0.5f * dy, -0.5f * dx);
            float s, c;
            sincospif(-(float)k * (1.0f / 8192.0f), &s, &c);
            float2 WFo = make_float2(c * Fo.x - s * Fo.y, c * Fo.y + s * Fo.x);
            float2 Xk = make_float2(Fe.x + WFo.x,  Fe.y + WFo.y);
            float2 Xj = make_float2(Fe.x - WFo.x, -(Fe.y - WFo.y));
            float2 Kk = Kf[k], Kj = Kf[j];
            float2 Yk = make_float2(Xk.x * Kk.x - Xk.y * Kk.y, Xk.x * Kk.y + Xk.y * Kk.x);
            float2 Yj = make_float2(Xj.x * Kj.x - Xj.y * Kj.y, Xj.x * Kj.y + Xj.y * Kj.x);
            // Ge = (Yk + conj(Yj))/2 ; Go = conj(W) * (Yk - conj(Yj))/2
            float2 Ge = make_float2(0.5f * (Yk.x + Yj.x), 0.5f * (Yk.y - Yj.y));
            float2 Gd = make_float2(0.5f * (Yk.x - Yj.x), 0.5f * (Yk.y + Yj.y));
            float2 Go = make_float2(c * Gd.x + s * Gd.y, c * Gd.y - s * Gd.x);
            Z[ra] = make_float2(Ge.x - Go.y, Ge.y + Go.x);          // Ge + i*Go
            Z[rb] = make_float2(Ge.x + Go.y, Go.x - Ge.y);          // conj(Ge)+i*conj(Go)
        }
    }

    fft_inv_stages(Z, tw);

    // final inverse stage (m=4096) fused with output: only first half needed
    float bv = bias[d];
    const float scl = 1.0f / (float)N2;
#pragma unroll
    for (int it = 0; it < 4096 / NT; it++) {
        int i = tid + it * NT;
        float2 w = tw[i];                      // stage m=4096 table, conj inline
        float2 zb = Z[i + 4096];
        float tx = zb.x * w.x + zb.y * w.y;
        float ty = zb.y * w.x - zb.x * w.y;
        float2 za = Z[i];
        xrow[i] = make_float2(fmaf(za.x + tx, scl, bv), fmaf(za.y + ty, scl, bv));
    }
}

// ============================================================================
// launch
// ============================================================================
extern "C" void kernel_launch(void* const* d_in, const int* in_sizes, int n_in,
                              void* d_out, int out_size) {
    (void)in_sizes; (void)n_in; (void)out_size;
    const float* x       = (const float*)d_in[0];
    const float* w_in    = (const float*)d_in[1];
    const float* b_in    = (const float*)d_in[2];
    const float* freq_in = (const float*)d_in[3];
    const float* w_h0    = (const float*)d_in[4];
    const float* b_h0    = (const float*)d_in[5];
    const float* freq_h0 = (const float*)d_in[6];
    const float* w_h1    = (const float*)d_in[7];
    const float* b_h1    = (const float*)d_in[8];
    const float* freq_h1 = (const float*)d_in[9];
    const float* w_out   = (const float*)d_in[10];
    const float* bias    = (const float*)d_in[11];
    float* out = (float*)d_out;

    const int smemBytes = 16384 * sizeof(float2);   // 128 KB (tw + Z)
    static int attrSet = 0;
    if (!attrSet) {
        cudaFuncSetAttribute(kfft_kernel,    cudaFuncAttributeMaxDynamicSharedMemorySize, smemBytes);
        cudaFuncSetAttribute(fftconv_kernel, cudaFuncAttributeMaxDynamicSharedMemorySize, smemBytes);
        attrSet = 1;
    }

    twfill_kernel<<<1, 1024>>>();
    mlp_kernel<<<SEQLEN, FO>>>(w_in, b_in, freq_in, w_h0, b_h0, freq_h0, w_h1, b_h1, freq_h1);
    kgemm_kernel<<<dim3(SEQLEN / 128, HD / 32), 256>>>(w_out);
    kfft_kernel<<<HD, NT, smemBytes>>>();
    transpose_in<<<dim3(SEQLEN / 32, HD / 32, NB), dim3(32, 8)>>>(x);
    fftconv_kernel<<<NB * HD, NT, smemBytes>>>(bias);
    transpose_out<<<dim3(SEQLEN / 32, HD / 32, NB), dim3(32, 8)>>>(out);
}

// round 4
// speedup vs baseline: 2.0578x; 2.0578x over previous
#include <cuda_runtime.h>
#include <cuda_bf16.h>
#include <math.h>

// ---------------- problem constants ----------------
#define SEQLEN   8192
#define HD       768
#define NB       8
#define FO       64
#define N2       8192
#define NFFT     16384
#define NT       512

// ---------------- device scratch ----------------
__device__ float  g_h   [SEQLEN * FO];
__device__ float  g_kT  [HD * SEQLEN];
__device__ float2 g_Kfp1[HD * 4097];                  // Kf[remap(idx)]
__device__ float2 g_Kfp2[HD * 4097];                  // Kf[8192-remap(idx)]
__device__ float  g_xT  [(size_t)NB * HD * SEQLEN];   // x transposed; y in-place
__device__ float2 g_tw  [N2];                         // per-stage contiguous twiddles
__device__ float2 g_wkp [4096];                       // W(remap(idx)) = e^{-i pi k/8192}

// ---------------- helpers ----------------
__device__ __forceinline__ int swz(int i) { return i ^ ((i >> 4) & 15); }
__device__ __forceinline__ float2 cmul(float2 a, float2 b) {
    return make_float2(a.x * b.x - a.y * b.y, a.x * b.y + a.y * b.x);
}
__device__ __forceinline__ float2 cmulc(float2 a, float2 b) {   // a * conj(b)
    return make_float2(a.x * b.x + a.y * b.y, a.y * b.x - a.x * b.y);
}

// ============================================================================
// Twiddle tables (gmem, once):
//  g_tw: stage half-size m at offset 8192-2m, entries e^{-i pi p/m}
//  g_wkp[idx] = e^{-i pi k/8192},  k = remap(idx) = (idx&31)<<7 | idx>>5
// ============================================================================
__global__ void twfill_kernel() {
    int off = 0;
    for (int m = 4096; m >= 1; m >>= 1) {
        for (int p = threadIdx.x; p < m; p += 1024) {
            float s, c;
            sincospif(-(float)p / (float)m, &s, &c);
            g_tw[off + p] = make_float2(c, s);
        }
        off += m;
    }
    for (int idx = threadIdx.x; idx < 4096; idx += 1024) {
        int k = ((idx & 31) << 7) | (idx >> 5);
        float s, c;
        sincospif(-(float)k * (1.0f / 8192.0f), &s, &c);
        g_wkp[idx] = make_float2(c, s);
    }
}

// ============================================================================
// Kernel A: implicit filter MLP
// ============================================================================
__global__ void mlp_kernel(const float* __restrict__ w_in, const float* __restrict__ b_in,
                           const float* __restrict__ freq_in,
                           const float* __restrict__ w_h0, const float* __restrict__ b_h0,
                           const float* __restrict__ freq_h0,
                           const float* __restrict__ w_h1, const float* __restrict__ b_h1,
                           const float* __restrict__ freq_h1) {
    __shared__ float hs[FO];
    int l = blockIdx.x;
    int j = threadIdx.x;

    float t   = (float)l * (1.0f / (float)(SEQLEN - 1));
    float wan = 6.283185307179586f * (float)l / (float)SEQLEN;
    float ph  = 1e-4f * wan;
    float z0 = t, z1 = cosf(ph), z2 = -sinf(ph);

    float a = fmaf(z0, w_in[j], fmaf(z1, w_in[FO + j], fmaf(z2, w_in[2 * FO + j], b_in[j])));
    hs[j] = sinf(freq_in[j] * a);
    __syncthreads();

    float acc = b_h0[j];
#pragma unroll
    for (int i = 0; i < FO; i++) acc = fmaf(hs[i], w_h0[i * FO + j], acc);
    float v = sinf(freq_h0[j] * acc);
    __syncthreads();
    hs[j] = v;
    __syncthreads();

    acc = b_h1[j];
#pragma unroll
    for (int i = 0; i < FO; i++) acc = fmaf(hs[i], w_h1[i * FO + j], acc);
    g_h[l * FO + j] = sinf(freq_h1[j] * acc);
}

// ============================================================================
// Kernel B: k^T[d][l] = (h[l] . w_out[:,d]) * exp(-t*|delta_d|)
// ============================================================================
__global__ void kgemm_kernel(const float* __restrict__ w_out) {
    __shared__ float hs[128][FO];
    __shared__ float ws[FO][32];
    int l0 = blockIdx.x * 128;
    int d0 = blockIdx.y * 32;
    int tid = threadIdx.x;   // 256

    for (int idx = tid; idx < 128 * FO; idx += 256)
        hs[idx >> 6][idx & 63] = g_h[(l0 + (idx >> 6)) * FO + (idx & 63)];
    for (int idx = tid; idx < FO * 32; idx += 256)
        ws[idx >> 5][idx & 31] = w_out[(idx >> 5) * HD + d0 + (idx & 31)];
    __syncthreads();

    int dx = tid & 31, ly = tid >> 5;
    int d = d0 + dx;
    const float ln001 = -4.605170185988091f;
    float mind = ln001 / 1.5f, maxd = ln001 / 0.3f;
    float delta = mind + (maxd - mind) * ((float)d / (float)(HD - 1));
    float ad = fabsf(delta);

    for (int ls = ly; ls < 128; ls += 8) {
        float acc = 0.f;
#pragma unroll
        for (int i = 0; i < FO; i++) acc = fmaf(hs[ls][i], ws[i][dx], acc);
        int l = l0 + ls;
        float t = (float)l * (1.0f / (float)(SEQLEN - 1));
        g_kT[(size_t)d * SEQLEN + l] = acc * expf(-t * ad);
    }
}

// ============================================================================
// FFT machinery: N2=8192 complex, NT=512 threads, swizzled smem layout.
// Forward DIF: fused m=4096, radix-4 x4 (q=1024,256,64,16), register tail m=8..1
// Inverse DIT: register tail m=1..8, radix-4 x4, fused m=4096 with store
// ============================================================================
__device__ __forceinline__ void load_tw(float2* tw) {
    const float4* src = (const float4*)g_tw;
    float4* dst = (float4*)tw;
#pragma unroll
    for (int it = 0; it < 4096 / NT; it++)
        dst[threadIdx.x + it * NT] = src[threadIdx.x + it * NT];
}

__device__ __forceinline__ void fwd_r4(float2* Z, const float2* tw, int q) {
    int ow1 = 8192 - 4 * q;   // table for stage 2q
    int ow2 = 8192 - 2 * q;   // table for stage q
    __syncthreads();
#pragma unroll
    for (int it = 0; it < 4; it++) {
        int i = threadIdx.x + it * NT;
        int p = i & (q - 1);
        int a = 4 * i - 3 * p;
        int i0 = swz(a), i1 = swz(a + q), i2 = swz(a + 2 * q), i3 = swz(a + 3 * q);
        float2 x0 = Z[i0], x1 = Z[i1], x2 = Z[i2], x3 = Z[i3];
        float2 w1 = tw[ow1 + p], w2 = tw[ow2 + p];
        float2 u0 = make_float2(x0.x + x2.x, x0.y + x2.y);
        float2 u1 = make_float2(x1.x + x3.x, x1.y + x3.y);
        float2 d0 = make_float2(x0.x - x2.x, x0.y - x2.y);
        float2 d1 = make_float2(x1.x - x3.x, x1.y - x3.y);
        float2 v0 = cmul(d0, w1);
        float2 t1 = cmul(d1, w1);
        float2 v1 = make_float2(t1.y, -t1.x);          // * (-i)
        Z[i0] = make_float2(u0.x + u1.x, u0.y + u1.y);
        Z[i1] = cmul(make_float2(u0.x - u1.x, u0.y - u1.y), w2);
        Z[i2] = make_float2(v0.x + v1.x, v0.y + v1.y);
        Z[i3] = cmul(make_float2(v0.x - v1.x, v0.y - v1.y), w2);
    }
}

__device__ __forceinline__ void inv_r4(float2* Z, const float2* tw, int q) {
    int owq  = 8192 - 2 * q;   // table stage q
    int ow2q = 8192 - 4 * q;   // table stage 2q
    __syncthreads();
#pragma unroll
    for (int it = 0; it < 4; it++) {
        int i = threadIdx.x + it * NT;
        int p = i & (q - 1);
        int a = 4 * i - 3 * p;
        int i0 = swz(a), i1 = swz(a + q), i2 = swz(a + 2 * q), i3 = swz(a + 3 * q);
        float2 x0 = Z[i0], x1 = Z[i1], x2 = Z[i2], x3 = Z[i3];
        float2 wq = tw[owq + p], w2 = tw[ow2q + p];
        float2 t1 = cmulc(x1, wq), t3 = cmulc(x3, wq);
        float2 u0 = make_float2(x0.x + t1.x, x0.y + t1.y);
        float2 u1 = make_float2(x0.x - t1.x, x0.y - t1.y);
        float2 u2 = make_float2(x2.x + t3.x, x2.y + t3.y);
        float2 u3 = make_float2(x2.x - t3.x, x2.y - t3.y);
        float2 s2  = cmulc(u2, w2);
        float2 s3t = cmulc(u3, w2);
        float2 s3  = make_float2(-s3t.y, s3t.x);       // * (+i)
        Z[i0] = make_float2(u0.x + s2.x, u0.y + s2.y);
        Z[i2] = make_float2(u0.x - s2.x, u0.y - s2.y);
        Z[i1] = make_float2(u1.x + s3.x, u1.y + s3.y);
        Z[i3] = make_float2(u1.x - s3.x, u1.y - s3.y);
    }
}

#define W8_INIT { \
    make_float2( 1.f, 0.f), \
    make_float2( 0.9238795325112867f, -0.3826834323650898f), \
    make_float2( 0.7071067811865476f, -0.7071067811865476f), \
    make_float2( 0.3826834323650898f, -0.9238795325112867f), \
    make_float2( 0.f, -1.f), \
    make_float2(-0.3826834323650898f, -0.9238795325112867f), \
    make_float2(-0.7071067811865476f, -0.7071067811865476f), \
    make_float2(-0.9238795325112867f, -0.3826834323650898f) }

// forward register tail: stages m=8,4,2,1 within 16-element blocks
__device__ __forceinline__ void fwd_tail(float2* Z) {
    const float2 W8[8] = W8_INIT;
    __syncthreads();
    int base = threadIdx.x * 16;
    float2 r[16];
#pragma unroll
    for (int o = 0; o < 16; o++) r[o] = Z[swz(base + o)];
#pragma unroll
    for (int m = 8; m >= 1; m >>= 1) {
#pragma unroll
        for (int g = 0; g < 16; g += 2 * m) {
#pragma unroll
            for (int p = 0; p < m; p++) {
                int a = g + p, b = a + m;
                float2 za = r[a], zb = r[b];
                r[a] = make_float2(za.x + zb.x, za.y + zb.y);
                float2 t = make_float2(za.x - zb.x, za.y - zb.y);
                r[b] = cmul(t, W8[p * (8 / m)]);
            }
        }
    }
#pragma unroll
    for (int o = 0; o < 16; o++) Z[swz(base + o)] = r[o];
}

// inverse register tail: stages m=1,2,4,8 (conj twiddles)
__device__ __forceinline__ void inv_tail(float2* Z) {
    const float2 W8[8] = W8_INIT;
    __syncthreads();
    int base = threadIdx.x * 16;
    float2 r[16];
#pragma unroll
    for (int o = 0; o < 16; o++) r[o] = Z[swz(base + o)];
#pragma unroll
    for (int m = 1; m <= 8; m <<= 1) {
#pragma unroll
        for (int g = 0; g < 16; g += 2 * m) {
#pragma unroll
            for (int p = 0; p < m; p++) {
                int a = g + p, b = a + m;
                float2 za = r[a], zb = r[b];
                float2 t = cmulc(zb, W8[p * (8 / m)]);
                r[a] = make_float2(za.x + t.x, za.y + t.y);
                r[b] = make_float2(za.x - t.x, za.y - t.y);
            }
        }
    }
#pragma unroll
    for (int o = 0; o < 16; o++) Z[swz(base + o)] = r[o];
}

__device__ __forceinline__ int brev13(int k) {
    return (int)(__brev((unsigned)k) >> 19);
}

// ============================================================================
// Kernel C: filter spectrum, permuted storage.  One CTA per d.
// ============================================================================
__global__ void __launch_bounds__(NT) kfft_kernel() {
    extern __shared__ float2 sm[];
    float2* tw = sm;
    float2* Z  = sm + 8192;
    int d = blockIdx.x, tid = threadIdx.x;

    load_tw(tw);
    __syncthreads();

    const float2* krow = (const float2*)(g_kT + (size_t)d * SEQLEN);
#pragma unroll
    for (int it = 0; it < 8; it++) {
        int i = tid + it * NT;
        float2 v = krow[i];
        float2 w = tw[i];
        Z[swz(i)] = v;
        Z[swz(i + 4096)] = cmul(v, w);
    }
    fwd_r4(Z, tw, 1024); fwd_r4(Z, tw, 256); fwd_r4(Z, tw, 64); fwd_r4(Z, tw, 16);
    fwd_tail(Z);

    const float invN = 1.0f / (float)NFFT;
    float2* K1 = g_Kfp1 + (size_t)d * 4097;
    float2* K2 = g_Kfp2 + (size_t)d * 4097;
    __syncthreads();
#pragma unroll
    for (int it = 0; it < 8; it++) {
        int idx = tid + it * NT;
        int k = ((idx & 31) << 7) | (idx >> 5);
        if (idx == 0) {
            float2 A = Z[0];
            K1[0] = make_float2((A.x + A.y) * invN, 0.f);
            K2[0] = make_float2((A.x - A.y) * invN, 0.f);
            float2 A1 = Z[1];                      // brev13(4096)=1, swz(1)=1
            K1[4096] = make_float2(A1.x * invN, -A1.y * invN);
            K2[4096] = make_float2(0.f, 0.f);
        } else {
            int j = 8192 - k;
            float2 A  = Z[swz(brev13(k))];
            float2 Bv = Z[swz(brev13(j))];
            float2 Fe = make_float2(0.5f * (A.x + Bv.x), 0.5f * (A.y - Bv.y));
            float dx = A.x - Bv.x, dy = A.y + Bv.y;
            float2 Fo = make_float2(0.5f * dy, -0.5f * dx);
            float2 W = g_wkp[idx];
            float c = W.x, s = W.y;
            float2 WFo = make_float2(c * Fo.x - s * Fo.y, c * Fo.y + s * Fo.x);
            K1[idx] = make_float2((Fe.x + WFo.x) * invN,  (Fe.y + WFo.y) * invN);
            K2[idx] = make_float2((Fe.x - WFo.x) * invN, -(Fe.y - WFo.y) * invN);
        }
    }
}

// ============================================================================
// Transposes
// ============================================================================
__global__ void transpose_in(const float* __restrict__ x) {
    __shared__ float tile[32][33];
    int b = blockIdx.z;
    int l0 = blockIdx.x << 5, d0 = blockIdx.y << 5;
    int tx = threadIdx.x, ty = threadIdx.y;
#pragma unroll
    for (int r = 0; r < 4; r++) {
        int l = l0 + ty + r * 8;
        tile[ty + r * 8][tx] = x[((size_t)b * SEQLEN + l) * HD + d0 + tx];
    }
    __syncthreads();
#pragma unroll
    for (int r = 0; r < 4; r++) {
        int d = d0 + ty + r * 8;
        g_xT[((size_t)b * HD + d) * SEQLEN + l0 + tx] = tile[tx][ty + r * 8];
    }
}

__global__ void transpose_out(float* __restrict__ out) {
    __shared__ float tile[32][33];
    int b = blockIdx.z;
    int l0 = blockIdx.x << 5, d0 = blockIdx.y << 5;
    int tx = threadIdx.x, ty = threadIdx.y;
#pragma unroll
    for (int r = 0; r < 4; r++) {
        int d = d0 + ty + r * 8;
        tile[ty + r * 8][tx] = g_xT[((size_t)b * HD + d) * SEQLEN + l0 + tx];
    }
    __syncthreads();
#pragma unroll
    for (int r = 0; r < 4; r++) {
        int l = l0 + ty + r * 8;
        out[((size_t)b * SEQLEN + l) * HD + d0 + tx] = tile[tx][ty + r * 8];
    }
}

// ============================================================================
// Kernel D: per-channel FFT convolution, in-place on xT row.
// ============================================================================
__global__ void __launch_bounds__(NT) fftconv_kernel(const float* __restrict__ bias) {
    extern __shared__ float2 sm[];
    float2* tw = sm;
    float2* Z  = sm + 8192;
    int bd = blockIdx.x, tid = threadIdx.x;
    int d = bd % HD;

    load_tw(tw);
    __syncthreads();

    float2* xrow = (float2*)(g_xT + (size_t)bd * SEQLEN);
#pragma unroll
    for (int it = 0; it < 8; it++) {
        int i = tid + it * NT;
        float2 v = xrow[i];
        float2 w = tw[i];
        Z[swz(i)] = v;
        Z[swz(i + 4096)] = cmul(v, w);
    }
    fwd_r4(Z, tw, 1024); fwd_r4(Z, tw, 256); fwd_r4(Z, tw, 64); fwd_r4(Z, tw, 16);
    fwd_tail(Z);

    // unpack -> X[k], multiply by Kf, repack (bit-reversed, swizzled, remapped)
    const float2* K1 = g_Kfp1 + (size_t)d * 4097;
    const float2* K2 = g_Kfp2 + (size_t)d * 4097;
    __syncthreads();
#pragma unroll
    for (int it = 0; it < 8; it++) {
        int idx = tid + it * NT;
        int k = ((idx & 31) << 7) | (idx >> 5);
        if (idx == 0) {
            // k = 0 (DC + Nyquist of the 16384-FFT, packed)
            float2 A = Z[0];
            float X0 = A.x + A.y, XN = A.x - A.y;
            float2 K0 = K1[0], KN = K2[0];
            float2 Y0 = make_float2(X0 * K0.x, X0 * K0.y);
            float2 YN = make_float2(XN * KN.x, XN * KN.y);
            float2 Ge = make_float2(0.5f * (Y0.x + YN.x), 0.5f * (Y0.y - YN.y));
            float2 Go = make_float2(0.5f * (Y0.x - YN.x), 0.5f * (Y0.y + YN.y));
            Z[0] = make_float2(Ge.x - Go.y, Ge.y + Go.x);
            // k = 4096 (self-paired): X = conj(Z[1]); Z[1] = conj(X*K)
            float2 A1 = Z[1];
            float2 Kq = K1[4096];
            float2 X = make_float2(A1.x, -A1.y);
            float2 Y = cmul(X, Kq);
            Z[1] = make_float2(Y.x, -Y.y);
        } else {
            int j = 8192 - k;
            int ra = swz(brev13(k));
            int rb = swz(brev13(j));
            float2 A  = Z[ra];
            float2 Bv = Z[rb];
            float2 Fe = make_float2(0.5f * (A.x + Bv.x), 0.5f * (A.y - Bv.y));
            float dx = A.x - Bv.x, dy = A.y + Bv.y;
            float2 Fo = make_float2(0.5f * dy, -0.5f * dx);
            float2 W = g_wkp[idx];
            float c = W.x, s = W.y;
            float2 WFo = make_float2(c * Fo.x - s * Fo.y, c * Fo.y + s * Fo.x);
            float2 Xk = make_float2(Fe.x + WFo.x,  Fe.y + WFo.y);
            float2 Xj = make_float2(Fe.x - WFo.x, -(Fe.y - WFo.y));
            float2 Kk = K1[idx], Kj = K2[idx];
            float2 Yk = cmul(Xk, Kk), Yj = cmul(Xj, Kj);
            float2 Ge = make_float2(0.5f * (Yk.x + Yj.x), 0.5f * (Yk.y - Yj.y));
            float2 Gd = make_float2(0.5f * (Yk.x - Yj.x), 0.5f * (Yk.y + Yj.y));
            float2 Go = make_float2(c * Gd.x + s * Gd.y, c * Gd.y - s * Gd.x);
            Z[ra] = make_float2(Ge.x - Go.y, Ge.y + Go.x);
            Z[rb] = make_float2(Ge.x + Go.y, Go.x - Ge.y);
        }
    }

    inv_tail(Z);
    inv_r4(Z, tw, 16); inv_r4(Z, tw, 64); inv_r4(Z, tw, 256); inv_r4(Z, tw, 1024);

    // final inverse stage m=4096 fused with store (first half only)
    __syncthreads();
    float bv = bias[d];
    const float scl = 1.0f / (float)N2;
#pragma unroll
    for (int it = 0; it < 8; it++) {
        int i = tid + it * NT;
        float2 w = tw[i];
        float2 zb = Z[swz(i + 4096)];
        float tx = zb.x * w.x + zb.y * w.y;
        float ty = zb.y * w.x - zb.x * w.y;
        float2 za = Z[swz(i)];
        xrow[i] = make_float2(fmaf(za.x + tx, scl, bv), fmaf(za.y + ty, scl, bv));
    }
}

// ============================================================================
// launch
// ============================================================================
extern "C" void kernel_launch(void* const* d_in, const int* in_sizes, int n_in,
                              void* d_out, int out_size) {
    (void)in_sizes; (void)n_in; (void)out_size;
    const float* x       = (const float*)d_in[0];
    const float* w_in    = (const float*)d_in[1];
    const float* b_in    = (const float*)d_in[2];
    const float* freq_in = (const float*)d_in[3];
    const float* w_h0    = (const float*)d_in[4];
    const float* b_h0    = (const float*)d_in[5];
    const float* freq_h0 = (const float*)d_in[6];
    const float* w_h1    = (const float*)d_in[7];
    const float* b_h1    = (const float*)d_in[8];
    const float* freq_h1 = (const float*)d_in[9];
    const float* w_out   = (const float*)d_in[10];
    const float* bias    = (const float*)d_in[11];
    float* out = (float*)d_out;

    const int smemBytes = 16384 * sizeof(float2);   // 128 KB
    cudaFuncSetAttribute(kfft_kernel,    cudaFuncAttributeMaxDynamicSharedMemorySize, smemBytes);
    cudaFuncSetAttribute(fftconv_kernel, cudaFuncAttributeMaxDynamicSharedMemorySize, smemBytes);

    twfill_kernel<<<1, 1024>>>();
    mlp_kernel<<<SEQLEN, FO>>>(w_in, b_in, freq_in, w_h0, b_h0, freq_h0, w_h1, b_h1, freq_h1);
    kgemm_kernel<<<dim3(SEQLEN / 128, HD / 32), 256>>>(w_out);
    kfft_kernel<<<HD, NT, smemBytes>>>();
    transpose_in<<<dim3(SEQLEN / 32, HD / 32, NB), dim3(32, 8)>>>(x);
    fftconv_kernel<<<NB * HD, NT, smemBytes>>>(bias);
    transpose_out<<<dim3(SEQLEN / 32, HD / 32, NB), dim3(32, 8)>>>(out);
}

// round 5
// speedup vs baseline: 2.5098x; 1.2197x over previous
#include <cuda_runtime.h>
#include <cuda_bf16.h>
#include <math.h>

// ---------------- problem constants ----------------
#define SEQLEN   8192
#define HD       768
#define NB       8
#define FO       64
#define N2       8192
#define NFFT     16384
#define NT       512

// ---------------- device scratch ----------------
__device__ float  g_h   [SEQLEN * FO];
__device__ float  g_kT  [HD * SEQLEN];
__device__ float2 g_Kfp1[HD * 4097];                  // Kf[remap(idx)]
__device__ float2 g_Kfp2[HD * 4097];                  // Kf[8192-remap(idx)]
__device__ float  g_xT  [(size_t)NB * HD * SEQLEN];   // x transposed; y in-place
__device__ float2 g_tw  [N2];                         // per-stage contiguous twiddles
__device__ float2 g_wkp [4096];                       // W(remap(idx)) = e^{-i pi k/8192}

// ---------------- helpers ----------------
__device__ __forceinline__ int swz(int i) { return i ^ ((i >> 4) & 15); }
__device__ __forceinline__ float2 cmul(float2 a, float2 b) {
    return make_float2(a.x * b.x - a.y * b.y, a.x * b.y + a.y * b.x);
}
__device__ __forceinline__ float2 cmulc(float2 a, float2 b) {   // a * conj(b)
    return make_float2(a.x * b.x + a.y * b.y, a.y * b.x - a.x * b.y);
}
__device__ __forceinline__ float2 ldtw(int i) {
    return __ldg(&g_tw[i]);
}

// ============================================================================
// Twiddle tables (gmem, once):
//  g_tw: stage half-size m at offset 8192-2m, entries e^{-i pi p/m}
//  g_wkp[idx] = e^{-i pi k/8192},  k = remap(idx) = (idx&31)<<7 | idx>>5
// ============================================================================
__global__ void twfill_kernel() {
    int off = 0;
    for (int m = 4096; m >= 1; m >>= 1) {
        for (int p = threadIdx.x; p < m; p += 1024) {
            float s, c;
            sincospif(-(float)p / (float)m, &s, &c);
            g_tw[off + p] = make_float2(c, s);
        }
        off += m;
    }
    for (int idx = threadIdx.x; idx < 4096; idx += 1024) {
        int k = ((idx & 31) << 7) | (idx >> 5);
        float s, c;
        sincospif(-(float)k * (1.0f / 8192.0f), &s, &c);
        g_wkp[idx] = make_float2(c, s);
    }
}

// ============================================================================
// Kernel A: implicit filter MLP
// ============================================================================
__global__ void mlp_kernel(const float* __restrict__ w_in, const float* __restrict__ b_in,
                           const float* __restrict__ freq_in,
                           const float* __restrict__ w_h0, const float* __restrict__ b_h0,
                           const float* __restrict__ freq_h0,
                           const float* __restrict__ w_h1, const float* __restrict__ b_h1,
                           const float* __restrict__ freq_h1) {
    __shared__ float hs[FO];
    int l = blockIdx.x;
    int j = threadIdx.x;

    float t   = (float)l * (1.0f / (float)(SEQLEN - 1));
    float wan = 6.283185307179586f * (float)l / (float)SEQLEN;
    float ph  = 1e-4f * wan;
    float z0 = t, z1 = cosf(ph), z2 = -sinf(ph);

    float a = fmaf(z0, w_in[j], fmaf(z1, w_in[FO + j], fmaf(z2, w_in[2 * FO + j], b_in[j])));
    hs[j] = sinf(freq_in[j] * a);
    __syncthreads();

    float acc = b_h0[j];
#pragma unroll
    for (int i = 0; i < FO; i++) acc = fmaf(hs[i], w_h0[i * FO + j], acc);
    float v = sinf(freq_h0[j] * acc);
    __syncthreads();
    hs[j] = v;
    __syncthreads();

    acc = b_h1[j];
#pragma unroll
    for (int i = 0; i < FO; i++) acc = fmaf(hs[i], w_h1[i * FO + j], acc);
    g_h[l * FO + j] = sinf(freq_h1[j] * acc);
}

// ============================================================================
// Kernel B: k^T[d][l] = (h[l] . w_out[:,d]) * exp(-t*|delta_d|)
// ============================================================================
__global__ void kgemm_kernel(const float* __restrict__ w_out) {
    __shared__ float hs[128][FO];
    __shared__ float ws[FO][32];
    int l0 = blockIdx.x * 128;
    int d0 = blockIdx.y * 32;
    int tid = threadIdx.x;   // 256

    for (int idx = tid; idx < 128 * FO; idx += 256)
        hs[idx >> 6][idx & 63] = g_h[(l0 + (idx >> 6)) * FO + (idx & 63)];
    for (int idx = tid; idx < FO * 32; idx += 256)
        ws[idx >> 5][idx & 31] = w_out[(idx >> 5) * HD + d0 + (idx & 31)];
    __syncthreads();

    int dx = tid & 31, ly = tid >> 5;
    int d = d0 + dx;
    const float ln001 = -4.605170185988091f;
    float mind = ln001 / 1.5f, maxd = ln001 / 0.3f;
    float delta = mind + (maxd - mind) * ((float)d / (float)(HD - 1));
    float ad = fabsf(delta);

    for (int ls = ly; ls < 128; ls += 8) {
        float acc = 0.f;
#pragma unroll
        for (int i = 0; i < FO; i++) acc = fmaf(hs[ls][i], ws[i][dx], acc);
        int l = l0 + ls;
        float t = (float)l * (1.0f / (float)(SEQLEN - 1));
        g_kT[(size_t)d * SEQLEN + l] = acc * expf(-t * ad);
    }
}

// ============================================================================
// FFT machinery: N2=8192 complex, NT=512 threads, swizzled smem Z (64 KB).
// Twiddles read straight from gmem (L1-cached, shared across all CTAs).
// Forward DIF: fused m=4096, radix-4 x4 (q=1024,256,64,16), register tail m=8..1
// Inverse DIT: register tail m=1..8, radix-4 x4, fused m=4096 with store
// ============================================================================
__device__ __forceinline__ void fwd_r4(float2* Z, int q) {
    int ow1 = 8192 - 4 * q;   // table for stage 2q
    int ow2 = 8192 - 2 * q;   // table for stage q
    __syncthreads();
#pragma unroll
    for (int it = 0; it < 4; it++) {
        int i = threadIdx.x + it * NT;
        int p = i & (q - 1);
        int a = 4 * i - 3 * p;
        int i0 = swz(a), i1 = swz(a + q), i2 = swz(a + 2 * q), i3 = swz(a + 3 * q);
        float2 x0 = Z[i0], x1 = Z[i1], x2 = Z[i2], x3 = Z[i3];
        float2 w1 = ldtw(ow1 + p), w2 = ldtw(ow2 + p);
        float2 u0 = make_float2(x0.x + x2.x, x0.y + x2.y);
        float2 u1 = make_float2(x1.x + x3.x, x1.y + x3.y);
        float2 d0 = make_float2(x0.x - x2.x, x0.y - x2.y);
        float2 d1 = make_float2(x1.x - x3.x, x1.y - x3.y);
        float2 v0 = cmul(d0, w1);
        float2 t1 = cmul(d1, w1);
        float2 v1 = make_float2(t1.y, -t1.x);          // * (-i)
        Z[i0] = make_float2(u0.x + u1.x, u0.y + u1.y);
        Z[i1] = cmul(make_float2(u0.x - u1.x, u0.y - u1.y), w2);
        Z[i2] = make_float2(v0.x + v1.x, v0.y + v1.y);
        Z[i3] = cmul(make_float2(v0.x - v1.x, v0.y - v1.y), w2);
    }
}

__device__ __forceinline__ void inv_r4(float2* Z, int q) {
    int owq  = 8192 - 2 * q;   // table stage q
    int ow2q = 8192 - 4 * q;   // table stage 2q
    __syncthreads();
#pragma unroll
    for (int it = 0; it < 4; it++) {
        int i = threadIdx.x + it * NT;
        int p = i & (q - 1);
        int a = 4 * i - 3 * p;
        int i0 = swz(a), i1 = swz(a + q), i2 = swz(a + 2 * q), i3 = swz(a + 3 * q);
        float2 x0 = Z[i0], x1 = Z[i1], x2 = Z[i2], x3 = Z[i3];
        float2 wq = ldtw(owq + p), w2 = ldtw(ow2q + p);
        float2 t1 = cmulc(x1, wq), t3 = cmulc(x3, wq);
        float2 u0 = make_float2(x0.x + t1.x, x0.y + t1.y);
        float2 u1 = make_float2(x0.x - t1.x, x0.y - t1.y);
        float2 u2 = make_float2(x2.x + t3.x, x2.y + t3.y);
        float2 u3 = make_float2(x2.x - t3.x, x2.y - t3.y);
        float2 s2  = cmulc(u2, w2);
        float2 s3t = cmulc(u3, w2);
        float2 s3  = make_float2(-s3t.y, s3t.x);       // * (+i)
        Z[i0] = make_float2(u0.x + s2.x, u0.y + s2.y);
        Z[i2] = make_float2(u0.x - s2.x, u0.y - s2.y);
        Z[i1] = make_float2(u1.x + s3.x, u1.y + s3.y);
        Z[i3] = make_float2(u1.x - s3.x, u1.y - s3.y);
    }
}

#define W8_INIT { \
    make_float2( 1.f, 0.f), \
    make_float2( 0.9238795325112867f, -0.3826834323650898f), \
    make_float2( 0.7071067811865476f, -0.7071067811865476f), \
    make_float2( 0.3826834323650898f, -0.9238795325112867f), \
    make_float2( 0.f, -1.f), \
    make_float2(-0.3826834323650898f, -0.9238795325112867f), \
    make_float2(-0.7071067811865476f, -0.7071067811865476f), \
    make_float2(-0.9238795325112867f, -0.3826834323650898f) }

// forward register tail: stages m=8,4,2,1 within 16-element blocks
__device__ __forceinline__ void fwd_tail(float2* Z) {
    const float2 W8[8] = W8_INIT;
    __syncthreads();
    int base = threadIdx.x * 16;
    float2 r[16];
#pragma unroll
    for (int o = 0; o < 16; o++) r[o] = Z[swz(base + o)];
#pragma unroll
    for (int m = 8; m >= 1; m >>= 1) {
#pragma unroll
        for (int g = 0; g < 16; g += 2 * m) {
#pragma unroll
            for (int p = 0; p < m; p++) {
                int a = g + p, b = a + m;
                float2 za = r[a], zb = r[b];
                r[a] = make_float2(za.x + zb.x, za.y + zb.y);
                float2 t = make_float2(za.x - zb.x, za.y - zb.y);
                r[b] = cmul(t, W8[p * (8 / m)]);
            }
        }
    }
#pragma unroll
    for (int o = 0; o < 16; o++) Z[swz(base + o)] = r[o];
}

// inverse register tail: stages m=1,2,4,8 (conj twiddles)
__device__ __forceinline__ void inv_tail(float2* Z) {
    const float2 W8[8] = W8_INIT;
    __syncthreads();
    int base = threadIdx.x * 16;
    float2 r[16];
#pragma unroll
    for (int o = 0; o < 16; o++) r[o] = Z[swz(base + o)];
#pragma unroll
    for (int m = 1; m <= 8; m <<= 1) {
#pragma unroll
        for (int g = 0; g < 16; g += 2 * m) {
#pragma unroll
            for (int p = 0; p < m; p++) {
                int a = g + p, b = a + m;
                float2 za = r[a], zb = r[b];
                float2 t = cmulc(zb, W8[p * (8 / m)]);
                r[a] = make_float2(za.x + t.x, za.y + t.y);
                r[b] = make_float2(za.x - t.x, za.y - t.y);
            }
        }
    }
#pragma unroll
    for (int o = 0; o < 16; o++) Z[swz(base + o)] = r[o];
}

__device__ __forceinline__ int brev13(int k) {
    return (int)(__brev((unsigned)k) >> 19);
}

// ============================================================================
// Kernel C: filter spectrum, permuted storage.  One CTA per d.
// ============================================================================
__global__ void __launch_bounds__(NT, 2) kfft_kernel() {
    extern __shared__ float2 sm[];
    float2* Z = sm;                       // 8192 float2 = 64 KB
    int d = blockIdx.x, tid = threadIdx.x;

    const float2* krow = (const float2*)(g_kT + (size_t)d * SEQLEN);
#pragma unroll
    for (int it = 0; it < 8; it++) {
        int i = tid + it * NT;
        float2 v = krow[i];
        float2 w = ldtw(i);               // stage m=4096 table at offset 0
        Z[swz(i)] = v;
        Z[swz(i + 4096)] = cmul(v, w);
    }
    fwd_r4(Z, 1024); fwd_r4(Z, 256); fwd_r4(Z, 64); fwd_r4(Z, 16);
    fwd_tail(Z);

    const float invN = 1.0f / (float)NFFT;
    float2* K1 = g_Kfp1 + (size_t)d * 4097;
    float2* K2 = g_Kfp2 + (size_t)d * 4097;
    __syncthreads();
#pragma unroll
    for (int it = 0; it < 8; it++) {
        int idx = tid + it * NT;
        int k = ((idx & 31) << 7) | (idx >> 5);
        if (idx == 0) {
            float2 A = Z[0];
            K1[0] = make_float2((A.x + A.y) * invN, 0.f);
            K2[0] = make_float2((A.x - A.y) * invN, 0.f);
            float2 A1 = Z[1];                      // brev13(4096)=1, swz(1)=1
            K1[4096] = make_float2(A1.x * invN, -A1.y * invN);
            K2[4096] = make_float2(0.f, 0.f);
        } else {
            int j = 8192 - k;
            float2 A  = Z[swz(brev13(k))];
            float2 Bv = Z[swz(brev13(j))];
            float2 Fe = make_float2(0.5f * (A.x + Bv.x), 0.5f * (A.y - Bv.y));
            float dx = A.x - Bv.x, dy = A.y + Bv.y;
            float2 Fo = make_float2(0.5f * dy, -0.5f * dx);
            float2 W = __ldg(&g_wkp[idx]);
            float c = W.x, s = W.y;
            float2 WFo = make_float2(c * Fo.x - s * Fo.y, c * Fo.y + s * Fo.x);
            K1[idx] = make_float2((Fe.x + WFo.x) * invN,  (Fe.y + WFo.y) * invN);
            K2[idx] = make_float2((Fe.x - WFo.x) * invN, -(Fe.y - WFo.y) * invN);
        }
    }
}

// ============================================================================
// Transposes
// ============================================================================
__global__ void transpose_in(const float* __restrict__ x) {
    __shared__ float tile[32][33];
    int b = blockIdx.z;
    int l0 = blockIdx.x << 5, d0 = blockIdx.y << 5;
    int tx = threadIdx.x, ty = threadIdx.y;
#pragma unroll
    for (int r = 0; r < 4; r++) {
        int l = l0 + ty + r * 8;
        tile[ty + r * 8][tx] = x[((size_t)b * SEQLEN + l) * HD + d0 + tx];
    }
    __syncthreads();
#pragma unroll
    for (int r = 0; r < 4; r++) {
        int d = d0 + ty + r * 8;
        g_xT[((size_t)b * HD + d) * SEQLEN + l0 + tx] = tile[tx][ty + r * 8];
    }
}

__global__ void transpose_out(float* __restrict__ out) {
    __shared__ float tile[32][33];
    int b = blockIdx.z;
    int l0 = blockIdx.x << 5, d0 = blockIdx.y << 5;
    int tx = threadIdx.x, ty = threadIdx.y;
#pragma unroll
    for (int r = 0; r < 4; r++) {
        int d = d0 + ty + r * 8;
        tile[ty + r * 8][tx] = g_xT[((size_t)b * HD + d) * SEQLEN + l0 + tx];
    }
    __syncthreads();
#pragma unroll
    for (int r = 0; r < 4; r++) {
        int l = l0 + ty + r * 8;
        out[((size_t)b * SEQLEN + l) * HD + d0 + tx] = tile[tx][ty + r * 8];
    }
}

// ============================================================================
// Kernel D: per-channel FFT convolution, in-place on xT row.
// ============================================================================
__global__ void __launch_bounds__(NT, 2) fftconv_kernel(const float* __restrict__ bias) {
    extern __shared__ float2 sm[];
    float2* Z = sm;                       // 8192 float2 = 64 KB
    int bd = blockIdx.x, tid = threadIdx.x;
    int d = bd % HD;

    float2* xrow = (float2*)(g_xT + (size_t)bd * SEQLEN);
#pragma unroll
    for (int it = 0; it < 8; it++) {
        int i = tid + it * NT;
        float2 v = xrow[i];
        float2 w = ldtw(i);
        Z[swz(i)] = v;
        Z[swz(i + 4096)] = cmul(v, w);
    }
    fwd_r4(Z, 1024); fwd_r4(Z, 256); fwd_r4(Z, 64); fwd_r4(Z, 16);
    fwd_tail(Z);

    // unpack -> X[k], multiply by Kf, repack (bit-reversed, swizzled, remapped)
    const float2* K1 = g_Kfp1 + (size_t)d * 4097;
    const float2* K2 = g_Kfp2 + (size_t)d * 4097;
    __syncthreads();
#pragma unroll
    for (int it = 0; it < 8; it++) {
        int idx = tid + it * NT;
        int k = ((idx & 31) << 7) | (idx >> 5);
        if (idx == 0) {
            // k = 0 (DC + Nyquist of the 16384-FFT, packed)
            float2 A = Z[0];
            float X0 = A.x + A.y, XN = A.x - A.y;
            float2 K0 = K1[0], KN = K2[0];
            float2 Y0 = make_float2(X0 * K0.x, X0 * K0.y);
            float2 YN = make_float2(XN * KN.x, XN * KN.y);
            float2 Ge = make_float2(0.5f * (Y0.x + YN.x), 0.5f * (Y0.y - YN.y));
            float2 Go = make_float2(0.5f * (Y0.x - YN.x), 0.5f * (Y0.y + YN.y));
            Z[0] = make_float2(Ge.x - Go.y, Ge.y + Go.x);
            // k = 4096 (self-paired): X = conj(Z[1]); Z[1] = conj(X*K)
            float2 A1 = Z[1];
            float2 Kq = K1[4096];
            float2 X = make_float2(A1.x, -A1.y);
            float2 Y = cmul(X, Kq);
            Z[1] = make_float2(Y.x, -Y.y);
        } else {
            int j = 8192 - k;
            int ra = swz(brev13(k));
            int rb = swz(brev13(j));
            float2 A  = Z[ra];
            float2 Bv = Z[rb];
            float2 Fe = make_float2(0.5f * (A.x + Bv.x), 0.5f * (A.y - Bv.y));
            float dx = A.x - Bv.x, dy = A.y + Bv.y;
            float2 Fo = make_float2(0.5f * dy, -0.5f * dx);
            float2 W = __ldg(&g_wkp[idx]);
            float c = W.x, s = W.y;
            float2 WFo = make_float2(c * Fo.x - s * Fo.y, c * Fo.y + s * Fo.x);
            float2 Xk = make_float2(Fe.x + WFo.x,  Fe.y + WFo.y);
            float2 Xj = make_float2(Fe.x - WFo.x, -(Fe.y - WFo.y));
            float2 Kk = K1[idx], Kj = K2[idx];
            float2 Yk = cmul(Xk, Kk), Yj = cmul(Xj, Kj);
            float2 Ge = make_float2(0.5f * (Yk.x + Yj.x), 0.5f * (Yk.y - Yj.y));
            float2 Gd = make_float2(0.5f * (Yk.x - Yj.x), 0.5f * (Yk.y + Yj.y));
            float2 Go = make_float2(c * Gd.x + s * Gd.y, c * Gd.y - s * Gd.x);
            Z[ra] = make_float2(Ge.x - Go.y, Ge.y + Go.x);
            Z[rb] = make_float2(Ge.x + Go.y, Go.x - Ge.y);
        }
    }

    inv_tail(Z);
    inv_r4(Z, 16); inv_r4(Z, 64); inv_r4(Z, 256); inv_r4(Z, 1024);

    // final inverse stage m=4096 fused with store (first half only)
    __syncthreads();
    float bv = bias[d];
    const float scl = 1.0f / (float)N2;
#pragma unroll
    for (int it = 0; it < 8; it++) {
        int i = tid + it * NT;
        float2 w = ldtw(i);
        float2 zb = Z[swz(i + 4096)];
        float tx = zb.x * w.x + zb.y * w.y;
        float ty = zb.y * w.x - zb.x * w.y;
        float2 za = Z[swz(i)];
        xrow[i] = make_float2(fmaf(za.x + tx, scl, bv), fmaf(za.y + ty, scl, bv));
    }
}

// ============================================================================
// launch
// ============================================================================
extern "C" void kernel_launch(void* const* d_in, const int* in_sizes, int n_in,
                              void* d_out, int out_size) {
    (void)in_sizes; (void)n_in; (void)out_size;
    const float* x       = (const float*)d_in[0];
    const float* w_in    = (const float*)d_in[1];
    const float* b_in    = (const float*)d_in[2];
    const float* freq_in = (const float*)d_in[3];
    const float* w_h0    = (const float*)d_in[4];
    const float* b_h0    = (const float*)d_in[5];
    const float* freq_h0 = (const float*)d_in[6];
    const float* w_h1    = (const float*)d_in[7];
    const float* b_h1    = (const float*)d_in[8];
    const float* freq_h1 = (const float*)d_in[9];
    const float* w_out   = (const float*)d_in[10];
    const float* bias    = (const float*)d_in[11];
    float* out = (float*)d_out;

    const int smemBytes = 8192 * sizeof(float2);   // 64 KB (Z only)
    cudaFuncSetAttribute(kfft_kernel,    cudaFuncAttributeMaxDynamicSharedMemorySize, smemBytes);
    cudaFuncSetAttribute(fftconv_kernel, cudaFuncAttributeMaxDynamicSharedMemorySize, smemBytes);

    twfill_kernel<<<1, 1024>>>();
    mlp_kernel<<<SEQLEN, FO>>>(w_in, b_in, freq_in, w_h0, b_h0, freq_h0, w_h1, b_h1, freq_h1);
    kgemm_kernel<<<dim3(SEQLEN / 128, HD / 32), 256>>>(w_out);
    kfft_kernel<<<HD, NT, smemBytes>>>();
    transpose_in<<<dim3(SEQLEN / 32, HD / 32, NB), dim3(32, 8)>>>(x);
    fftconv_kernel<<<NB * HD, NT, smemBytes>>>(bias);
    transpose_out<<<dim3(SEQLEN / 32, HD / 32, NB), dim3(32, 8)>>>(out);
}

// round 6
// speedup vs baseline: 2.7059x; 1.0781x over previous
#include <cuda_runtime.h>
#include <cuda_bf16.h>
#include <math.h>

// ---------------- problem constants ----------------
#define SEQLEN   8192
#define HD       768
#define NB       8
#define FO       64
#define N2       8192
#define NFFT     16384
#define NT       512

// ---------------- device scratch ----------------
__device__ float  g_h   [SEQLEN * FO];
__device__ float  g_kT  [HD * SEQLEN];
__device__ float2 g_Kfp1[HD * 4097];                  // Kf[remap(idx)]
__device__ float2 g_Kfp2[HD * 4097];                  // Kf[8192-remap(idx)]
__device__ float  g_xT  [(size_t)NB * HD * SEQLEN];   // x transposed; y in-place
__device__ float2 g_tw  [N2];                         // per-stage contiguous twiddles
__device__ float2 g_wkp [4096];                       // W(remap(idx)) = e^{-i pi k/8192}

// ---------------- helpers ----------------
__device__ __forceinline__ int swz(int i) { return i ^ ((i >> 4) & 15); }
__device__ __forceinline__ float2 cmul(float2 a, float2 b) {
    return make_float2(a.x * b.x - a.y * b.y, a.x * b.y + a.y * b.x);
}
__device__ __forceinline__ float2 cmulc(float2 a, float2 b) {   // a * conj(b)
    return make_float2(a.x * b.x + a.y * b.y, a.y * b.x - a.x * b.y);
}

// ============================================================================
// Twiddle tables (gmem, once):
//  g_tw: stage half-size m at offset 8192-2m, entries e^{-i pi p/m}
//  g_wkp[idx] = e^{-i pi k/8192},  k = remap(idx) = (idx&31)<<7 | idx>>5
// ============================================================================
__global__ void twfill_kernel() {
    int off = 0;
    for (int m = 4096; m >= 1; m >>= 1) {
        for (int p = threadIdx.x; p < m; p += 1024) {
            float s, c;
            sincospif(-(float)p / (float)m, &s, &c);
            g_tw[off + p] = make_float2(c, s);
        }
        off += m;
    }
    for (int idx = threadIdx.x; idx < 4096; idx += 1024) {
        int k = ((idx & 31) << 7) | (idx >> 5);
        float s, c;
        sincospif(-(float)k * (1.0f / 8192.0f), &s, &c);
        g_wkp[idx] = make_float2(c, s);
    }
}

// ============================================================================
// Kernel A: implicit filter MLP
// ============================================================================
__global__ void mlp_kernel(const float* __restrict__ w_in, const float* __restrict__ b_in,
                           const float* __restrict__ freq_in,
                           const float* __restrict__ w_h0, const float* __restrict__ b_h0,
                           const float* __restrict__ freq_h0,
                           const float* __restrict__ w_h1, const float* __restrict__ b_h1,
                           const float* __restrict__ freq_h1) {
    __shared__ float hs[FO];
    int l = blockIdx.x;
    int j = threadIdx.x;

    float t   = (float)l * (1.0f / (float)(SEQLEN - 1));
    float wan = 6.283185307179586f * (float)l / (float)SEQLEN;
    float ph  = 1e-4f * wan;
    float z0 = t, z1 = cosf(ph), z2 = -sinf(ph);

    float a = fmaf(z0, w_in[j], fmaf(z1, w_in[FO + j], fmaf(z2, w_in[2 * FO + j], b_in[j])));
    hs[j] = sinf(freq_in[j] * a);
    __syncthreads();

    float acc = b_h0[j];
#pragma unroll
    for (int i = 0; i < FO; i++) acc = fmaf(hs[i], w_h0[i * FO + j], acc);
    float v = sinf(freq_h0[j] * acc);
    __syncthreads();
    hs[j] = v;
    __syncthreads();

    acc = b_h1[j];
#pragma unroll
    for (int i = 0; i < FO; i++) acc = fmaf(hs[i], w_h1[i * FO + j], acc);
    g_h[l * FO + j] = sinf(freq_h1[j] * acc);
}

// ============================================================================
// Kernel B: k^T[d][l] = (h[l] . w_out[:,d]) * exp(-t*|delta_d|)
// ============================================================================
__global__ void kgemm_kernel(const float* __restrict__ w_out) {
    __shared__ float hs[128][FO];
    __shared__ float ws[FO][32];
    int l0 = blockIdx.x * 128;
    int d0 = blockIdx.y * 32;
    int tid = threadIdx.x;   // 256

    for (int idx = tid; idx < 128 * FO; idx += 256)
        hs[idx >> 6][idx & 63] = g_h[(l0 + (idx >> 6)) * FO + (idx & 63)];
    for (int idx = tid; idx < FO * 32; idx += 256)
        ws[idx >> 5][idx & 31] = w_out[(idx >> 5) * HD + d0 + (idx & 31)];
    __syncthreads();

    int dx = tid & 31, ly = tid >> 5;
    int d = d0 + dx;
    const float ln001 = -4.605170185988091f;
    float mind = ln001 / 1.5f, maxd = ln001 / 0.3f;
    float delta = mind + (maxd - mind) * ((float)d / (float)(HD - 1));
    float ad = fabsf(delta);

    for (int ls = ly; ls < 128; ls += 8) {
        float acc = 0.f;
#pragma unroll
        for (int i = 0; i < FO; i++) acc = fmaf(hs[ls][i], ws[i][dx], acc);
        int l = l0 + ls;
        float t = (float)l * (1.0f / (float)(SEQLEN - 1));
        g_kT[(size_t)d * SEQLEN + l] = acc * expf(-t * ad);
    }
}

// ============================================================================
// Register-blocked FFT core (N2 = 8192 complex, NT = 512 threads).
// 13 stages in 3 register partitions of 16 elements + 2 smem exchanges:
//   P1 (stride-256, per half): fused gmem load + m=4096..256
//   P2 (stride-16):            m=128..16       (writes XOR-swizzled)
//   P3 (contig-16 tail):       m=8..1          (swizzled layout)
// Inverse mirrors. Unpack and fused store operate on the same layouts as before.
// ============================================================================

// forward butterfly stage on r[16]: pair distance D, twiddle p = pbase + STEP*jj
template<int D, int STEP>
__device__ __forceinline__ void fwd_stage(float2* r, int off, int pbase) {
#pragma unroll
    for (int j0 = 0; j0 < 16; j0 += 2 * D) {
#pragma unroll
        for (int jj = 0; jj < D; jj++) {
            int j = j0 + jj;
            float2 w = __ldg(&g_tw[off + pbase + STEP * jj]);
            float2 a = r[j], b = r[j + D];
            r[j] = make_float2(a.x + b.x, a.y + b.y);
            float2 t = make_float2(a.x - b.x, a.y - b.y);
            r[j + D] = cmul(t, w);
        }
    }
}

template<int D, int STEP>
__device__ __forceinline__ void inv_stage(float2* r, int off, int pbase) {
#pragma unroll
    for (int j0 = 0; j0 < 16; j0 += 2 * D) {
#pragma unroll
        for (int jj = 0; jj < D; jj++) {
            int j = j0 + jj;
            float2 w = __ldg(&g_tw[off + pbase + STEP * jj]);
            float2 t = cmulc(r[j + D], w);
            float2 a = r[j];
            r[j]     = make_float2(a.x + t.x, a.y + t.y);
            r[j + D] = make_float2(a.x - t.x, a.y - t.y);
        }
    }
}

#define W8_INIT { \
    make_float2( 1.f, 0.f), \
    make_float2( 0.9238795325112867f, -0.3826834323650898f), \
    make_float2( 0.7071067811865476f, -0.7071067811865476f), \
    make_float2( 0.3826834323650898f, -0.9238795325112867f), \
    make_float2( 0.f, -1.f), \
    make_float2(-0.3826834323650898f, -0.9238795325112867f), \
    make_float2(-0.7071067811865476f, -0.7071067811865476f), \
    make_float2(-0.9238795325112867f, -0.3826834323650898f) }

// forward register tail: stages m=8,4,2,1 within 16-element blocks (swizzled)
__device__ __forceinline__ void fwd_tail(float2* Z) {
    const float2 W8[8] = W8_INIT;
    int base = threadIdx.x * 16;
    float2 r[16];
#pragma unroll
    for (int o = 0; o < 16; o++) r[o] = Z[swz(base + o)];
#pragma unroll
    for (int m = 8; m >= 1; m >>= 1) {
#pragma unroll
        for (int g = 0; g < 16; g += 2 * m) {
#pragma unroll
            for (int p = 0; p < m; p++) {
                int a = g + p, b = a + m;
                float2 za = r[a], zb = r[b];
                r[a] = make_float2(za.x + zb.x, za.y + zb.y);
                float2 t = make_float2(za.x - zb.x, za.y - zb.y);
                r[b] = cmul(t, W8[p * (8 / m)]);
            }
        }
    }
#pragma unroll
    for (int o = 0; o < 16; o++) Z[swz(base + o)] = r[o];
}

// inverse register tail: stages m=1,2,4,8 (conj twiddles), swizzled layout
__device__ __forceinline__ void inv_tail(float2* Z) {
    const float2 W8[8] = W8_INIT;
    int base = threadIdx.x * 16;
    float2 r[16];
#pragma unroll
    for (int o = 0; o < 16; o++) r[o] = Z[swz(base + o)];
#pragma unroll
    for (int m = 1; m <= 8; m <<= 1) {
#pragma unroll
        for (int g = 0; g < 16; g += 2 * m) {
#pragma unroll
            for (int p = 0; p < m; p++) {
                int a = g + p, b = a + m;
                float2 za = r[a], zb = r[b];
                float2 t = cmulc(zb, W8[p * (8 / m)]);
                r[a] = make_float2(za.x + t.x, za.y + t.y);
                r[b] = make_float2(za.x - t.x, za.y - t.y);
            }
        }
    }
#pragma unroll
    for (int o = 0; o < 16; o++) Z[swz(base + o)] = r[o];
}

// Full forward FFT: src = 4096 float2 (the real row, viewed as complex pairs).
// Leaves Z in bit-reversed, swizzled layout.
__device__ __forceinline__ void fft_fwd_8k(float2* Z, const float2* __restrict__ src) {
    int t = threadIdx.x;
    float2 r[16];
    {
        int h = t >> 8, c = t & 255;
        if (h == 0) {
#pragma unroll
            for (int j = 0; j < 16; j++) r[j] = src[c + 256 * j];
        } else {
#pragma unroll
            for (int j = 0; j < 16; j++) {
                float2 v = src[c + 256 * j];
                r[j] = cmul(v, __ldg(&g_tw[c + 256 * j]));   // fused zero-pad stage m=4096
            }
        }
        fwd_stage<8, 256>(r, 4096, c);   // m=2048
        fwd_stage<4, 256>(r, 6144, c);   // m=1024
        fwd_stage<2, 256>(r, 7168, c);   // m=512
        fwd_stage<1, 256>(r, 7680, c);   // m=256
        int base = h * 4096 + c;
#pragma unroll
        for (int j = 0; j < 16; j++) Z[base + 256 * j] = r[j];
    }
    __syncthreads();
    {
        int ql = t & 15, g = t >> 4;
        int base = ql + 256 * g;
#pragma unroll
        for (int j = 0; j < 16; j++) r[j] = Z[base + 16 * j];
        __syncthreads();                  // all reads done before swizzled writes
        fwd_stage<8, 16>(r, 7936, ql);   // m=128
        fwd_stage<4, 16>(r, 8064, ql);   // m=64
        fwd_stage<2, 16>(r, 8128, ql);   // m=32
        fwd_stage<1, 16>(r, 8160, ql);   // m=16
#pragma unroll
        for (int j = 0; j < 16; j++) Z[(ql ^ j) + 16 * j + 256 * g] = r[j];
    }
    __syncthreads();
    fwd_tail(Z);                          // m=8..1 on own swizzled block
}

// Full inverse FFT up through m=2048 (final m=4096 stage is fused with the store).
// Input: bit-reversed swizzled Z (caller synced). Output: plain-layout Z.
__device__ __forceinline__ void fft_inv_8k(float2* Z) {
    int t = threadIdx.x;
    inv_tail(Z);                          // m=1..8 on own swizzled block
    __syncthreads();
    float2 r[16];
    {
        int ql = t & 15, g = t >> 4;
#pragma unroll
        for (int j = 0; j < 16; j++) r[j] = Z[(ql ^ j) + 16 * j + 256 * g];
        __syncthreads();                  // all swizzled reads before plain writes
        inv_stage<1, 16>(r, 8160, ql);   // m=16
        inv_stage<2, 16>(r, 8128, ql);   // m=32
        inv_stage<4, 16>(r, 8064, ql);   // m=64
        inv_stage<8, 16>(r, 7936, ql);   // m=128
        int base = ql + 256 * g;
#pragma unroll
        for (int j = 0; j < 16; j++) Z[base + 16 * j] = r[j];
    }
    __syncthreads();
    {
        int h = t >> 8, c = t & 255;
        int base = h * 4096 + c;
#pragma unroll
        for (int j = 0; j < 16; j++) r[j] = Z[base + 256 * j];
        inv_stage<1, 256>(r, 7680, c);   // m=256
        inv_stage<2, 256>(r, 7168, c);   // m=512
        inv_stage<4, 256>(r, 6144, c);   // m=1024
        inv_stage<8, 256>(r, 4096, c);   // m=2048
#pragma unroll
        for (int j = 0; j < 16; j++) Z[base + 256 * j] = r[j];
    }
    __syncthreads();
}

__device__ __forceinline__ int brev13(int k) {
    return (int)(__brev((unsigned)k) >> 19);
}

// ============================================================================
// Kernel C: filter spectrum, permuted storage.  One CTA per d.
// ============================================================================
__global__ void __launch_bounds__(NT, 2) kfft_kernel() {
    extern __shared__ float2 sm[];
    float2* Z = sm;                       // 8192 float2 = 64 KB
    int d = blockIdx.x, tid = threadIdx.x;

    fft_fwd_8k(Z, (const float2*)(g_kT + (size_t)d * SEQLEN));
    __syncthreads();

    const float invN = 1.0f / (float)NFFT;
    float2* K1 = g_Kfp1 + (size_t)d * 4097;
    float2* K2 = g_Kfp2 + (size_t)d * 4097;
#pragma unroll
    for (int it = 0; it < 8; it++) {
        int idx = tid + it * NT;
        int k = ((idx & 31) << 7) | (idx >> 5);
        if (idx == 0) {
            float2 A = Z[0];
            K1[0] = make_float2((A.x + A.y) * invN, 0.f);
            K2[0] = make_float2((A.x - A.y) * invN, 0.f);
            float2 A1 = Z[1];                      // brev13(4096)=1, swz(1)=1
            K1[4096] = make_float2(A1.x * invN, -A1.y * invN);
            K2[4096] = make_float2(0.f, 0.f);
        } else {
            int j = 8192 - k;
            float2 A  = Z[swz(brev13(k))];
            float2 Bv = Z[swz(brev13(j))];
            float2 Fe = make_float2(0.5f * (A.x + Bv.x), 0.5f * (A.y - Bv.y));
            float dx = A.x - Bv.x, dy = A.y + Bv.y;
            float2 Fo = make_float2(0.5f * dy, -0.5f * dx);
            float2 W = __ldg(&g_wkp[idx]);
            float c = W.x, s = W.y;
            float2 WFo = make_float2(c * Fo.x - s * Fo.y, c * Fo.y + s * Fo.x);
            K1[idx] = make_float2((Fe.x + WFo.x) * invN,  (Fe.y + WFo.y) * invN);
            K2[idx] = make_float2((Fe.x - WFo.x) * invN, -(Fe.y - WFo.y) * invN);
        }
    }
}

// ============================================================================
// Transposes
// ============================================================================
__global__ void transpose_in(const float* __restrict__ x) {
    __shared__ float tile[32][33];
    int b = blockIdx.z;
    int l0 = blockIdx.x << 5, d0 = blockIdx.y << 5;
    int tx = threadIdx.x, ty = threadIdx.y;
#pragma unroll
    for (int r = 0; r < 4; r++) {
        int l = l0 + ty + r * 8;
        tile[ty + r * 8][tx] = x[((size_t)b * SEQLEN + l) * HD + d0 + tx];
    }
    __syncthreads();
#pragma unroll
    for (int r = 0; r < 4; r++) {
        int d = d0 + ty + r * 8;
        g_xT[((size_t)b * HD + d) * SEQLEN + l0 + tx] = tile[tx][ty + r * 8];
    }
}

__global__ void transpose_out(float* __restrict__ out) {
    __shared__ float tile[32][33];
    int b = blockIdx.z;
    int l0 = blockIdx.x << 5, d0 = blockIdx.y << 5;
    int tx = threadIdx.x, ty = threadIdx.y;
#pragma unroll
    for (int r = 0; r < 4; r++) {
        int d = d0 + ty + r * 8;
        tile[ty + r * 8][tx] = g_xT[((size_t)b * HD + d) * SEQLEN + l0 + tx];
    }
    __syncthreads();
#pragma unroll
    for (int r = 0; r < 4; r++) {
        int l = l0 + ty + r * 8;
        out[((size_t)b * SEQLEN + l) * HD + d0 + tx] = tile[tx][ty + r * 8];
    }
}

// ============================================================================
// Kernel D: per-channel FFT convolution, in-place on xT row.
// ============================================================================
__global__ void __launch_bounds__(NT, 2) fftconv_kernel(const float* __restrict__ bias) {
    extern __shared__ float2 sm[];
    float2* Z = sm;                       // 8192 float2 = 64 KB
    int bd = blockIdx.x, tid = threadIdx.x;
    int d = bd % HD;

    float2* xrow = (float2*)(g_xT + (size_t)bd * SEQLEN);
    fft_fwd_8k(Z, xrow);
    __syncthreads();

    // unpack -> X[k], multiply by Kf, repack (bit-reversed, swizzled, remapped)
    const float2* K1 = g_Kfp1 + (size_t)d * 4097;
    const float2* K2 = g_Kfp2 + (size_t)d * 4097;
#pragma unroll
    for (int it = 0; it < 8; it++) {
        int idx = tid + it * NT;
        int k = ((idx & 31) << 7) | (idx >> 5);
        if (idx == 0) {
            // k = 0 (DC + Nyquist of the 16384-FFT, packed)
            float2 A = Z[0];
            float X0 = A.x + A.y, XN = A.x - A.y;
            float2 K0 = K1[0], KN = K2[0];
            float2 Y0 = make_float2(X0 * K0.x, X0 * K0.y);
            float2 YN = make_float2(XN * KN.x, XN * KN.y);
            float2 Ge = make_float2(0.5f * (Y0.x + YN.x), 0.5f * (Y0.y - YN.y));
            float2 Go = make_float2(0.5f * (Y0.x - YN.x), 0.5f * (Y0.y + YN.y));
            Z[0] = make_float2(Ge.x - Go.y, Ge.y + Go.x);
            // k = 4096 (self-paired): X = conj(Z[1]); Z[1] = conj(X*K)
            float2 A1 = Z[1];
            float2 Kq = K1[4096];
            float2 X = make_float2(A1.x, -A1.y);
            float2 Y = cmul(X, Kq);
            Z[1] = make_float2(Y.x, -Y.y);
        } else {
            int j = 8192 - k;
            int ra = swz(brev13(k));
            int rb = swz(brev13(j));
            float2 A  = Z[ra];
            float2 Bv = Z[rb];
            float2 Fe = make_float2(0.5f * (A.x + Bv.x), 0.5f * (A.y - Bv.y));
            float dx = A.x - Bv.x, dy = A.y + Bv.y;
            float2 Fo = make_float2(0.5f * dy, -0.5f * dx);
            float2 W = __ldg(&g_wkp[idx]);
            float c = W.x, s = W.y;
            float2 WFo = make_float2(c * Fo.x - s * Fo.y, c * Fo.y + s * Fo.x);
            float2 Xk = make_float2(Fe.x + WFo.x,  Fe.y + WFo.y);
            float2 Xj = make_float2(Fe.x - WFo.x, -(Fe.y - WFo.y));
            float2 Kk = K1[idx], Kj = K2[idx];
            float2 Yk = cmul(Xk, Kk), Yj = cmul(Xj, Kj);
            float2 Ge = make_float2(0.5f * (Yk.x + Yj.x), 0.5f * (Yk.y - Yj.y));
            float2 Gd = make_float2(0.5f * (Yk.x - Yj.x), 0.5f * (Yk.y + Yj.y));
            float2 Go = make_float2(c * Gd.x + s * Gd.y, c * Gd.y - s * Gd.x);
            Z[ra] = make_float2(Ge.x - Go.y, Ge.y + Go.x);
            Z[rb] = make_float2(Ge.x + Go.y, Go.x - Ge.y);
        }
    }
    __syncthreads();

    fft_inv_8k(Z);                        // leaves plain layout, synced

    // final inverse stage m=4096 fused with store (first half only), plain layout
    float bv = bias[d];
    const float scl = 1.0f / (float)N2;
#pragma unroll
    for (int it = 0; it < 8; it++) {
        int i = tid + it * NT;
        float2 w = __ldg(&g_tw[i]);
        float2 zb = Z[i + 4096];
        float tx = zb.x * w.x + zb.y * w.y;
        float ty = zb.y * w.x - zb.x * w.y;
        float2 za = Z[i];
        xrow[i] = make_float2(fmaf(za.x + tx, scl, bv), fmaf(za.y + ty, scl, bv));
    }
}

// ============================================================================
// launch
// ============================================================================
extern "C" void kernel_launch(void* const* d_in, const int* in_sizes, int n_in,
                              void* d_out, int out_size) {
    (void)in_sizes; (void)n_in; (void)out_size;
    const float* x       = (const float*)d_in[0];
    const float* w_in    = (const float*)d_in[1];
    const float* b_in    = (const float*)d_in[2];
    const float* freq_in = (const float*)d_in[3];
    const float* w_h0    = (const float*)d_in[4];
    const float* b_h0    = (const float*)d_in[5];
    const float* freq_h0 = (const float*)d_in[6];
    const float* w_h1    = (const float*)d_in[7];
    const float* b_h1    = (const float*)d_in[8];
    const float* freq_h1 = (const float*)d_in[9];
    const float* w_out   = (const float*)d_in[10];
    const float* bias    = (const float*)d_in[11];
    float* out = (float*)d_out;

    const int smemBytes = 8192 * sizeof(float2);   // 64 KB (Z only)
    cudaFuncSetAttribute(kfft_kernel,    cudaFuncAttributeMaxDynamicSharedMemorySize, smemBytes);
    cudaFuncSetAttribute(fftconv_kernel, cudaFuncAttributeMaxDynamicSharedMemorySize, smemBytes);

    twfill_kernel<<<1, 1024>>>();
    mlp_kernel<<<SEQLEN, FO>>>(w_in, b_in, freq_in, w_h0, b_h0, freq_h0, w_h1, b_h1, freq_h1);
    kgemm_kernel<<<dim3(SEQLEN / 128, HD / 32), 256>>>(w_out);
    kfft_kernel<<<HD, NT, smemBytes>>>();
    transpose_in<<<dim3(SEQLEN / 32, HD / 32, NB), dim3(32, 8)>>>(x);
    fftconv_kernel<<<NB * HD, NT, smemBytes>>>(bias);
    transpose_out<<<dim3(SEQLEN / 32, HD / 32, NB), dim3(32, 8)>>>(out);
}

// round 7
// speedup vs baseline: 2.7366x; 1.0113x over previous
#include <cuda_runtime.h>
#include <cuda_bf16.h>
#include <math.h>

// ---------------- problem constants ----------------
#define SEQLEN   8192
#define HD       768
#define NB       8
#define FO       64
#define N2       8192
#define NFFT     16384
#define NT       512

// ---------------- device scratch ----------------
__device__ float  g_h   [SEQLEN * FO];
__device__ float  g_kT  [HD * SEQLEN];
__device__ float2 g_Kfp1[HD * 4097];                  // Kf[remap(idx)]
__device__ float2 g_Kfp2[HD * 4097];                  // Kf[8192-remap(idx)]
__device__ float  g_xT  [(size_t)NB * HD * SEQLEN];   // x transposed; y in-place
__device__ float2 g_tw  [N2];                         // per-stage contiguous twiddles e^{-i pi p/m}
__device__ float2 g_tw3 [N2];                         // e^{-i 3 pi p/m}, same layout
__device__ float2 g_wkp [4096];                       // W(remap(idx)) = e^{-i pi k/8192}

// ---------------- helpers ----------------
__device__ __forceinline__ int swz(int i) { return i ^ ((i >> 4) & 15); }
__device__ __forceinline__ float2 cadd(float2 a, float2 b) { return make_float2(a.x + b.x, a.y + b.y); }
__device__ __forceinline__ float2 csub(float2 a, float2 b) { return make_float2(a.x - b.x, a.y - b.y); }
__device__ __forceinline__ float2 addim(float2 a, float2 b) { return make_float2(a.x - b.y, a.y + b.x); } // a + i*b
__device__ __forceinline__ float2 subim(float2 a, float2 b) { return make_float2(a.x + b.y, a.y - b.x); } // a - i*b
__device__ __forceinline__ float2 cmul(float2 a, float2 b) {
    return make_float2(a.x * b.x - a.y * b.y, a.x * b.y + a.y * b.x);
}
__device__ __forceinline__ float2 cmulc(float2 a, float2 b) {   // a * conj(b)
    return make_float2(a.x * b.x + a.y * b.y, a.y * b.x - a.x * b.y);
}

// ============================================================================
// Twiddle tables (gmem, once):
//  g_tw : stage half-size m at offset 8192-2m, entries e^{-i pi p/m}
//  g_tw3: same layout, entries e^{-i 3 pi p/m}
//  g_wkp[idx] = e^{-i pi k/8192},  k = remap(idx) = (idx&31)<<7 | idx>>5
// ============================================================================
__global__ void twfill_kernel() {
    int off = 0;
    for (int m = 4096; m >= 1; m >>= 1) {
        for (int p = threadIdx.x; p < m; p += 1024) {
            float s, c;
            sincospif(-(float)p / (float)m, &s, &c);
            g_tw[off + p] = make_float2(c, s);
            sincospif(-3.0f * (float)p / (float)m, &s, &c);
            g_tw3[off + p] = make_float2(c, s);
        }
        off += m;
    }
    for (int idx = threadIdx.x; idx < 4096; idx += 1024) {
        int k = ((idx & 31) << 7) | (idx >> 5);
        float s, c;
        sincospif(-(float)k * (1.0f / 8192.0f), &s, &c);
        g_wkp[idx] = make_float2(c, s);
    }
}

// ============================================================================
// Kernel A: implicit filter MLP
// ============================================================================
__global__ void mlp_kernel(const float* __restrict__ w_in, const float* __restrict__ b_in,
                           const float* __restrict__ freq_in,
                           const float* __restrict__ w_h0, const float* __restrict__ b_h0,
                           const float* __restrict__ freq_h0,
                           const float* __restrict__ w_h1, const float* __restrict__ b_h1,
                           const float* __restrict__ freq_h1) {
    __shared__ float hs[FO];
    int l = blockIdx.x;
    int j = threadIdx.x;

    float t   = (float)l * (1.0f / (float)(SEQLEN - 1));
    float wan = 6.283185307179586f * (float)l / (float)SEQLEN;
    float ph  = 1e-4f * wan;
    float z0 = t, z1 = cosf(ph), z2 = -sinf(ph);

    float a = fmaf(z0, w_in[j], fmaf(z1, w_in[FO + j], fmaf(z2, w_in[2 * FO + j], b_in[j])));
    hs[j] = sinf(freq_in[j] * a);
    __syncthreads();

    float acc = b_h0[j];
#pragma unroll
    for (int i = 0; i < FO; i++) acc = fmaf(hs[i], w_h0[i * FO + j], acc);
    float v = sinf(freq_h0[j] * acc);
    __syncthreads();
    hs[j] = v;
    __syncthreads();

    acc = b_h1[j];
#pragma unroll
    for (int i = 0; i < FO; i++) acc = fmaf(hs[i], w_h1[i * FO + j], acc);
    g_h[l * FO + j] = sinf(freq_h1[j] * acc);
}

// ============================================================================
// Kernel B: k^T[d][l] = (h[l] . w_out[:,d]) * exp(-t*|delta_d|)
// ============================================================================
__global__ void kgemm_kernel(const float* __restrict__ w_out) {
    __shared__ float hs[128][FO];
    __shared__ float ws[FO][32];
    int l0 = blockIdx.x * 128;
    int d0 = blockIdx.y * 32;
    int tid = threadIdx.x;   // 256

    for (int idx = tid; idx < 128 * FO; idx += 256)
        hs[idx >> 6][idx & 63] = g_h[(l0 + (idx >> 6)) * FO + (idx & 63)];
    for (int idx = tid; idx < FO * 32; idx += 256)
        ws[idx >> 5][idx & 31] = w_out[(idx >> 5) * HD + d0 + (idx & 31)];
    __syncthreads();

    int dx = tid & 31, ly = tid >> 5;
    int d = d0 + dx;
    const float ln001 = -4.605170185988091f;
    float mind = ln001 / 1.5f, maxd = ln001 / 0.3f;
    float delta = mind + (maxd - mind) * ((float)d / (float)(HD - 1));
    float ad = fabsf(delta);

    for (int ls = ly; ls < 128; ls += 8) {
        float acc = 0.f;
#pragma unroll
        for (int i = 0; i < FO; i++) acc = fmaf(hs[ls][i], ws[i][dx], acc);
        int l = l0 + ls;
        float t = (float)l * (1.0f / (float)(SEQLEN - 1));
        g_kT[(size_t)d * SEQLEN + l] = acc * expf(-t * ad);
    }
}

// ============================================================================
// Register-blocked FFT core (N2 = 8192 complex, NT = 512 threads), fused
// radix-4 (3-multiply) stages:
//   P1 (stride-256): fused gmem load+m=4096, then (2048,1024), (512,256)
//   P2 (stride-16):  (128,64), (32,16)
//   tail (contig16): (8,4), (2,1)      [constant twiddles]
// Inverse mirrors. Twiddles from gmem tables (L1-cached).
// ============================================================================

// Forward fused radix-4: stages 2q then q; D = q-distance in register units.
// o1 = g_tw offset of stage 2q, o2 = offset of stage q; W3 from g_tw3[o1+p].
template<int D, int STEP>
__device__ __forceinline__ void fwd4(float2* r, int o1, int o2, int pbase) {
#pragma unroll
    for (int jj = 0; jj < D; jj++) {
        int p = pbase + STEP * jj;
        float2 W1 = __ldg(&g_tw[o1 + p]);
        float2 W2 = __ldg(&g_tw[o2 + p]);
        float2 W3 = __ldg(&g_tw3[o1 + p]);
#pragma unroll
        for (int j0 = 0; j0 < 16; j0 += 4 * D) {
            int j = j0 + jj;
            float2 x0 = r[j], x1 = r[j + D], x2 = r[j + 2 * D], x3 = r[j + 3 * D];
            float2 u0 = cadd(x0, x2), u1 = cadd(x1, x3);
            float2 e  = csub(x0, x2), od = csub(x1, x3);
            r[j]         = cadd(u0, u1);
            r[j + D]     = cmul(csub(u0, u1), W2);
            r[j + 2 * D] = cmul(subim(e, od), W1);
            r[j + 3 * D] = cmul(addim(e, od), W3);
        }
    }
}

// Inverse fused radix-4: stages q then 2q (conjugated twiddles).
template<int D, int STEP>
__device__ __forceinline__ void inv4(float2* r, int o1, int o2, int pbase) {
#pragma unroll
    for (int jj = 0; jj < D; jj++) {
        int p = pbase + STEP * jj;
        float2 W1 = __ldg(&g_tw[o1 + p]);
        float2 W2 = __ldg(&g_tw[o2 + p]);
        float2 W3 = __ldg(&g_tw3[o1 + p]);
#pragma unroll
        for (int j0 = 0; j0 < 16; j0 += 4 * D) {
            int j = j0 + jj;
            float2 x0 = r[j], x1 = r[j + D], x2 = r[j + 2 * D], x3 = r[j + 3 * D];
            float2 p1 = cmulc(x1, W2), p2 = cmulc(x2, W1), p3 = cmulc(x3, W3);
            float2 A = cadd(x0, p1), C = csub(x0, p1);
            float2 B = cadd(p2, p3), Dp = csub(p2, p3);
            r[j]         = cadd(A, B);
            r[j + 2 * D] = csub(A, B);
            r[j + D]     = addim(C, Dp);
            r[j + 3 * D] = subim(C, Dp);
        }
    }
}

#define CW1_INIT { make_float2(1.f,0.f), make_float2(0.9238795325112867f,-0.3826834323650898f), \
                   make_float2(0.7071067811865476f,-0.7071067811865476f), make_float2(0.3826834323650898f,-0.9238795325112867f) }
#define CW2_INIT { make_float2(1.f,0.f), make_float2(0.7071067811865476f,-0.7071067811865476f), \
                   make_float2(0.f,-1.f), make_float2(-0.7071067811865476f,-0.7071067811865476f) }
#define CW3_INIT { make_float2(1.f,0.f), make_float2(0.3826834323650898f,-0.9238795325112867f), \
                   make_float2(-0.7071067811865476f,-0.7071067811865476f), make_float2(-0.9238795325112867f,0.3826834323650898f) }

// forward register tail: fused (8,4) then (2,1) within 16-element swizzled blocks
__device__ __forceinline__ void fwd_tail(float2* Z) {
    const float2 CW1[4] = CW1_INIT;
    const float2 CW2[4] = CW2_INIT;
    const float2 CW3[4] = CW3_INIT;
    int base = threadIdx.x * 16, s = threadIdx.x & 15;
    float2 r[16];
#pragma unroll
    for (int o = 0; o < 16; o++) r[o] = Z[base + (o ^ s)];
#pragma unroll
    for (int o = 0; o < 4; o++) {          // stages 8,4
        float2 x0 = r[o], x1 = r[o + 4], x2 = r[o + 8], x3 = r[o + 12];
        float2 u0 = cadd(x0, x2), u1 = cadd(x1, x3);
        float2 e  = csub(x0, x2), od = csub(x1, x3);
        r[o]      = cadd(u0, u1);
        r[o + 4]  = cmul(csub(u0, u1), CW2[o]);
        r[o + 8]  = cmul(subim(e, od), CW1[o]);
        r[o + 12] = cmul(addim(e, od), CW3[o]);
    }
#pragma unroll
    for (int a = 0; a < 16; a += 4) {      // stages 2,1 (twiddle-free)
        float2 x0 = r[a], x1 = r[a + 1], x2 = r[a + 2], x3 = r[a + 3];
        float2 u0 = cadd(x0, x2), u1 = cadd(x1, x3);
        float2 e  = csub(x0, x2), od = csub(x1, x3);
        r[a]     = cadd(u0, u1);
        r[a + 1] = csub(u0, u1);
        r[a + 2] = subim(e, od);
        r[a + 3] = addim(e, od);
    }
#pragma unroll
    for (int o = 0; o < 16; o++) Z[base + (o ^ s)] = r[o];
}

// inverse register tail: fused (1,2) then (4,8), swizzled layout
__device__ __forceinline__ void inv_tail(float2* Z) {
    const float2 CW1[4] = CW1_INIT;
    const float2 CW2[4] = CW2_INIT;
    const float2 CW3[4] = CW3_INIT;
    int base = threadIdx.x * 16, s = threadIdx.x & 15;
    float2 r[16];
#pragma unroll
    for (int o = 0; o < 16; o++) r[o] = Z[base + (o ^ s)];
#pragma unroll
    for (int a = 0; a < 16; a += 4) {      // stages 1,2 (twiddle-free)
        float2 x0 = r[a], x1 = r[a + 1], x2 = r[a + 2], x3 = r[a + 3];
        float2 a0 = cadd(x0, x1), a1 = csub(x0, x1);
        float2 a2 = cadd(x2, x3), a3 = csub(x2, x3);
        r[a]     = cadd(a0, a2);
        r[a + 2] = csub(a0, a2);
        r[a + 1] = addim(a1, a3);
        r[a + 3] = subim(a1, a3);
    }
#pragma unroll
    for (int o = 0; o < 4; o++) {          // stages 4,8
        float2 x0 = r[o], x1 = r[o + 4], x2 = r[o + 8], x3 = r[o + 12];
        float2 p1 = cmulc(x1, CW2[o]), p2 = cmulc(x2, CW1[o]), p3 = cmulc(x3, CW3[o]);
        float2 A = cadd(x0, p1), C = csub(x0, p1);
        float2 B = cadd(p2, p3), Dp = csub(p2, p3);
        r[o]      = cadd(A, B);
        r[o + 8]  = csub(A, B);
        r[o + 4]  = addim(C, Dp);
        r[o + 12] = subim(C, Dp);
    }
#pragma unroll
    for (int o = 0; o < 16; o++) Z[base + (o ^ s)] = r[o];
}

// Full forward FFT: src = 4096 float2. Leaves Z bit-reversed, swizzled.
__device__ __forceinline__ void fft_fwd_8k(float2* Z, const float2* __restrict__ src) {
    int t = threadIdx.x;
    float2 r[16];
    {
        int h = t >> 8, c = t & 255;
        if (h == 0) {
#pragma unroll
            for (int j = 0; j < 16; j++) r[j] = src[c + 256 * j];
        } else {
#pragma unroll
            for (int j = 0; j < 16; j++) {
                float2 v = src[c + 256 * j];
                r[j] = cmul(v, __ldg(&g_tw[c + 256 * j]));   // fused zero-pad stage m=4096
            }
        }
        fwd4<4, 256>(r, 4096, 6144, c);   // stages 2048,1024
        fwd4<1, 256>(r, 7168, 7680, c);   // stages 512,256
        int base = h * 4096 + c;
#pragma unroll
        for (int j = 0; j < 16; j++) Z[base + 256 * j] = r[j];
    }
    __syncthreads();
    {
        int ql = t & 15, g = t >> 4;
        int base = ql + 256 * g;
#pragma unroll
        for (int j = 0; j < 16; j++) r[j] = Z[base + 16 * j];
        __syncthreads();                  // all reads done before swizzled writes
        fwd4<4, 16>(r, 7936, 8064, ql);  // stages 128,64
        fwd4<1, 16>(r, 8128, 8160, ql);  // stages 32,16
#pragma unroll
        for (int j = 0; j < 16; j++) Z[(ql ^ j) + 16 * j + 256 * g] = r[j];
    }
    __syncthreads();
    fwd_tail(Z);                          // stages 8..1
}

// Full inverse FFT through m=2048 (final m=4096 fused with the store).
// Input: bit-reversed swizzled Z (caller synced). Output: plain-layout Z.
__device__ __forceinline__ void fft_inv_8k(float2* Z) {
    int t = threadIdx.x;
    inv_tail(Z);                          // stages 1..8
    __syncthreads();
    float2 r[16];
    {
        int ql = t & 15, g = t >> 4;
#pragma unroll
        for (int j = 0; j < 16; j++) r[j] = Z[(ql ^ j) + 16 * j + 256 * g];
        __syncthreads();                  // all swizzled reads before plain writes
        inv4<1, 16>(r, 8128, 8160, ql);  // stages 16,32
        inv4<4, 16>(r, 7936, 8064, ql);  // stages 64,128
        int base = ql + 256 * g;
#pragma unroll
        for (int j = 0; j < 16; j++) Z[base + 16 * j] = r[j];
    }
    __syncthreads();
    {
        int h = t >> 8, c = t & 255;
        int base = h * 4096 + c;
#pragma unroll
        for (int j = 0; j < 16; j++) r[j] = Z[base + 256 * j];
        inv4<1, 256>(r, 7168, 7680, c);  // stages 256,512
        inv4<4, 256>(r, 4096, 6144, c);  // stages 1024,2048
#pragma unroll
        for (int j = 0; j < 16; j++) Z[base + 256 * j] = r[j];
    }
    __syncthreads();
}

__device__ __forceinline__ int brev13(int k) {
    return (int)(__brev((unsigned)k) >> 19);
}

// ============================================================================
// Kernel C: filter spectrum, permuted storage.  One CTA per d.
// ============================================================================
__global__ void __launch_bounds__(NT, 2) kfft_kernel() {
    extern __shared__ float2 sm[];
    float2* Z = sm;                       // 8192 float2 = 64 KB
    int d = blockIdx.x, tid = threadIdx.x;

    fft_fwd_8k(Z, (const float2*)(g_kT + (size_t)d * SEQLEN));
    __syncthreads();

    const float invN = 1.0f / (float)NFFT;
    float2* K1 = g_Kfp1 + (size_t)d * 4097;
    float2* K2 = g_Kfp2 + (size_t)d * 4097;
#pragma unroll
    for (int it = 0; it < 8; it++) {
        int idx = tid + it * NT;
        int k = ((idx & 31) << 7) | (idx >> 5);
        if (idx == 0) {
            float2 A = Z[0];
            K1[0] = make_float2((A.x + A.y) * invN, 0.f);
            K2[0] = make_float2((A.x - A.y) * invN, 0.f);
            float2 A1 = Z[1];                      // brev13(4096)=1, swz(1)=1
            K1[4096] = make_float2(A1.x * invN, -A1.y * invN);
            K2[4096] = make_float2(0.f, 0.f);
        } else {
            int j = 8192 - k;
            float2 A  = Z[swz(brev13(k))];
            float2 Bv = Z[swz(brev13(j))];
            float2 Fe = make_float2(0.5f * (A.x + Bv.x), 0.5f * (A.y - Bv.y));
            float dx = A.x - Bv.x, dy = A.y + Bv.y;
            float2 Fo = make_float2(0.5f * dy, -0.5f * dx);
            float2 W = __ldg(&g_wkp[idx]);
            float c = W.x, s = W.y;
            float2 WFo = make_float2(c * Fo.x - s * Fo.y, c * Fo.y + s * Fo.x);
            K1[idx] = make_float2((Fe.x + WFo.x) * invN,  (Fe.y + WFo.y) * invN);
            K2[idx] = make_float2((Fe.x - WFo.x) * invN, -(Fe.y - WFo.y) * invN);
        }
    }
}

// ============================================================================
// Transposes
// ============================================================================
__global__ void transpose_in(const float* __restrict__ x) {
    __shared__ float tile[32][33];
    int b = blockIdx.z;
    int l0 = blockIdx.x << 5, d0 = blockIdx.y << 5;
    int tx = threadIdx.x, ty = threadIdx.y;
#pragma unroll
    for (int r = 0; r < 4; r++) {
        int l = l0 + ty + r * 8;
        tile[ty + r * 8][tx] = x[((size_t)b * SEQLEN + l) * HD + d0 + tx];
    }
    __syncthreads();
#pragma unroll
    for (int r = 0; r < 4; r++) {
        int d = d0 + ty + r * 8;
        g_xT[((size_t)b * HD + d) * SEQLEN + l0 + tx] = tile[tx][ty + r * 8];
    }
}

__global__ void transpose_out(float* __restrict__ out) {
    __shared__ float tile[32][33];
    int b = blockIdx.z;
    int l0 = blockIdx.x << 5, d0 = blockIdx.y << 5;
    int tx = threadIdx.x, ty = threadIdx.y;
#pragma unroll
    for (int r = 0; r < 4; r++) {
        int d = d0 + ty + r * 8;
        tile[ty + r * 8][tx] = g_xT[((size_t)b * HD + d) * SEQLEN + l0 + tx];
    }
    __syncthreads();
#pragma unroll
    for (int r = 0; r < 4; r++) {
        int l = l0 + ty + r * 8;
        out[((size_t)b * SEQLEN + l) * HD + d0 + tx] = tile[tx][ty + r * 8];
    }
}

// ============================================================================
// Kernel D: per-channel FFT convolution, in-place on xT row.
// ============================================================================
__global__ void __launch_bounds__(NT, 2) fftconv_kernel(const float* __restrict__ bias) {
    extern __shared__ float2 sm[];
    float2* Z = sm;                       // 8192 float2 = 64 KB
    int bd = blockIdx.x, tid = threadIdx.x;
    int d = bd % HD;

    float2* xrow = (float2*)(g_xT + (size_t)bd * SEQLEN);
    fft_fwd_8k(Z, xrow);
    __syncthreads();

    // unpack -> X[k], multiply by Kf, repack (bit-reversed, swizzled, remapped)
    const float2* K1 = g_Kfp1 + (size_t)d * 4097;
    const float2* K2 = g_Kfp2 + (size_t)d * 4097;
#pragma unroll
    for (int it = 0; it < 8; it++) {
        int idx = tid + it * NT;
        int k = ((idx & 31) << 7) | (idx >> 5);
        if (idx == 0) {
            // k = 0 (DC + Nyquist of the 16384-FFT, packed)
            float2 A = Z[0];
            float X0 = A.x + A.y, XN = A.x - A.y;
            float2 K0 = K1[0], KN = K2[0];
            float2 Y0 = make_float2(X0 * K0.x, X0 * K0.y);
            float2 YN = make_float2(XN * KN.x, XN * KN.y);
            float2 Ge = make_float2(0.5f * (Y0.x + YN.x), 0.5f * (Y0.y - YN.y));
            float2 Go = make_float2(0.5f * (Y0.x - YN.x), 0.5f * (Y0.y + YN.y));
            Z[0] = make_float2(Ge.x - Go.y, Ge.y + Go.x);
            // k = 4096 (self-paired): X = conj(Z[1]); Z[1] = conj(X*K)
            float2 A1 = Z[1];
            float2 Kq = K1[4096];
            float2 X = make_float2(A1.x, -A1.y);
            float2 Y = cmul(X, Kq);
            Z[1] = make_float2(Y.x, -Y.y);
        } else {
            int j = 8192 - k;
            int ra = swz(brev13(k));
            int rb = swz(brev13(j));
            float2 A  = Z[ra];
            float2 Bv = Z[rb];
            float2 Fe = make_float2(0.5f * (A.x + Bv.x), 0.5f * (A.y - Bv.y));
            float dx = A.x - Bv.x, dy = A.y + Bv.y;
            float2 Fo = make_float2(0.5f * dy, -0.5f * dx);
            float2 W = __ldg(&g_wkp[idx]);
            float c = W.x, s = W.y;
            float2 WFo = make_float2(c * Fo.x - s * Fo.y, c * Fo.y + s * Fo.x);
            float2 Xk = make_float2(Fe.x + WFo.x,  Fe.y + WFo.y);
            float2 Xj = make_float2(Fe.x - WFo.x, -(Fe.y - WFo.y));
            float2 Kk = K1[idx], Kj = K2[idx];
            float2 Yk = cmul(Xk, Kk), Yj = cmul(Xj, Kj);
            float2 Ge = make_float2(0.5f * (Yk.x + Yj.x), 0.5f * (Yk.y - Yj.y));
            float2 Gd = make_float2(0.5f * (Yk.x - Yj.x), 0.5f * (Yk.y + Yj.y));
            float2 Go = make_float2(c * Gd.x + s * Gd.y, c * Gd.y - s * Gd.x);
            Z[ra] = make_float2(Ge.x - Go.y, Ge.y + Go.x);
            Z[rb] = make_float2(Ge.x + Go.y, Go.x - Ge.y);
        }
    }
    __syncthreads();

    fft_inv_8k(Z);                        // leaves plain layout, synced

    // final inverse stage m=4096 fused with store (first half only), plain layout
    float bv = bias[d];
    const float scl = 1.0f / (float)N2;
#pragma unroll
    for (int it = 0; it < 8; it++) {
        int i = tid + it * NT;
        float2 w = __ldg(&g_tw[i]);
        float2 zb = Z[i + 4096];
        float tx = zb.x * w.x + zb.y * w.y;
        float ty = zb.y * w.x - zb.x * w.y;
        float2 za = Z[i];
        xrow[i] = make_float2(fmaf(za.x + tx, scl, bv), fmaf(za.y + ty, scl, bv));
    }
}

// ============================================================================
// launch
// ============================================================================
extern "C" void kernel_launch(void* const* d_in, const int* in_sizes, int n_in,
                              void* d_out, int out_size) {
    (void)in_sizes; (void)n_in; (void)out_size;
    const float* x       = (const float*)d_in[0];
    const float* w_in    = (const float*)d_in[1];
    const float* b_in    = (const float*)d_in[2];
    const float* freq_in = (const float*)d_in[3];
    const float* w_h0    = (const float*)d_in[4];
    const float* b_h0    = (const float*)d_in[5];
    const float* freq_h0 = (const float*)d_in[6];
    const float* w_h1    = (const float*)d_in[7];
    const float* b_h1    = (const float*)d_in[8];
    const float* freq_h1 = (const float*)d_in[9];
    const float* w_out   = (const float*)d_in[10];
    const float* bias    = (const float*)d_in[11];
    float* out = (float*)d_out;

    const int smemBytes = 8192 * sizeof(float2);   // 64 KB (Z only)
    cudaFuncSetAttribute(kfft_kernel,    cudaFuncAttributeMaxDynamicSharedMemorySize, smemBytes);
    cudaFuncSetAttribute(fftconv_kernel, cudaFuncAttributeMaxDynamicSharedMemorySize, smemBytes);

    twfill_kernel<<<1, 1024>>>();
    mlp_kernel<<<SEQLEN, FO>>>(w_in, b_in, freq_in, w_h0, b_h0, freq_h0, w_h1, b_h1, freq_h1);
    kgemm_kernel<<<dim3(SEQLEN / 128, HD / 32), 256>>>(w_out);
    kfft_kernel<<<HD, NT, smemBytes>>>();
    transpose_in<<<dim3(SEQLEN / 32, HD / 32, NB), dim3(32, 8)>>>(x);
    fftconv_kernel<<<NB * HD, NT, smemBytes>>>(bias);
    transpose_out<<<dim3(SEQLEN / 32, HD / 32, NB), dim3(32, 8)>>>(out);
}

// round 8
// speedup vs baseline: 2.8024x; 1.0240x over previous
#include <cuda_runtime.h>
#include <cuda_bf16.h>
#include <math.h>

// ---------------- problem constants ----------------
#define SEQLEN   8192
#define HD       768
#define NB       8
#define FO       64
#define N2       8192
#define NFFT     16384
#define NT       512

// ---------------- device scratch ----------------
__device__ float  g_h   [SEQLEN * FO];
__device__ float  g_kT  [HD * SEQLEN];
__device__ float2 g_Kfp1[HD * 4097];                  // Kf[remap(idx)]
__device__ float2 g_Kfp2[HD * 4097];                  // Kf[8192-remap(idx)]
__device__ float  g_xT  [(size_t)NB * HD * SEQLEN];   // x transposed; y in-place
__device__ float2 g_tw  [N2];                         // per-stage contiguous twiddles e^{-i pi p/m}
__device__ float2 g_tw3 [N2];                         // e^{-i 3 pi p/m}, same layout
__device__ float2 g_wkp [4096];                       // W(remap(idx)) = e^{-i pi k/8192}

// ---------------- helpers ----------------
__device__ __forceinline__ int swz(int i) { return i ^ ((i >> 4) & 15); }
__device__ __forceinline__ float2 cadd(float2 a, float2 b) { return make_float2(a.x + b.x, a.y + b.y); }
__device__ __forceinline__ float2 csub(float2 a, float2 b) { return make_float2(a.x - b.x, a.y - b.y); }
__device__ __forceinline__ float2 addim(float2 a, float2 b) { return make_float2(a.x - b.y, a.y + b.x); } // a + i*b
__device__ __forceinline__ float2 subim(float2 a, float2 b) { return make_float2(a.x + b.y, a.y - b.x); } // a - i*b
__device__ __forceinline__ float2 cmul(float2 a, float2 b) {
    return make_float2(a.x * b.x - a.y * b.y, a.x * b.y + a.y * b.x);
}
__device__ __forceinline__ float2 cmulc(float2 a, float2 b) {   // a * conj(b)
    return make_float2(a.x * b.x + a.y * b.y, a.y * b.x - a.x * b.y);
}

// ============================================================================
// Twiddle tables (gmem, once) — parallel fill, flat index -> (m, p) via clz:
//  g_tw : stage half-size m at offset 8192-2m, entries e^{-i pi p/m}
//  g_tw3: same layout, entries e^{-i 3 pi p/m}
//  g_wkp[idx] = e^{-i pi k/8192},  k = remap(idx) = (idx&31)<<7 | idx>>5
// ============================================================================
__global__ void twfill_kernel() {     // grid 32, block 256
    int gid = blockIdx.x * 256 + threadIdx.x;     // 0..8191
    if (gid == 8191) {
        g_tw[8191]  = make_float2(1.f, 0.f);
        g_tw3[8191] = make_float2(1.f, 0.f);
    } else {
        unsigned u = 8192u - (unsigned)gid;       // u in [2, 8192]
        int m = 1 << (31 - __clz(u - 1));         // m < u <= 2m
        int p = 2 * m - (int)u;
        float invm = 1.0f / (float)m;
        float s, c;
        sincospif(-(float)p * invm, &s, &c);
        g_tw[gid] = make_float2(c, s);
        sincospif(-3.0f * (float)p * invm, &s, &c);
        g_tw3[gid] = make_float2(c, s);
    }
    if (gid < 4096) {
        int k = ((gid & 31) << 7) | (gid >> 5);
        float s, c;
        sincospif(-(float)k * (1.0f / 8192.0f), &s, &c);
        g_wkp[gid] = make_float2(c, s);
    }
}

// ============================================================================
// Kernel A: implicit filter MLP
// ============================================================================
__global__ void mlp_kernel(const float* __restrict__ w_in, const float* __restrict__ b_in,
                           const float* __restrict__ freq_in,
                           const float* __restrict__ w_h0, const float* __restrict__ b_h0,
                           const float* __restrict__ freq_h0,
                           const float* __restrict__ w_h1, const float* __restrict__ b_h1,
                           const float* __restrict__ freq_h1) {
    __shared__ float hs[FO];
    int l = blockIdx.x;
    int j = threadIdx.x;

    float t   = (float)l * (1.0f / (float)(SEQLEN - 1));
    float wan = 6.283185307179586f * (float)l / (float)SEQLEN;
    float ph  = 1e-4f * wan;
    float z0 = t, z1 = cosf(ph), z2 = -sinf(ph);

    float a = fmaf(z0, w_in[j], fmaf(z1, w_in[FO + j], fmaf(z2, w_in[2 * FO + j], b_in[j])));
    hs[j] = sinf(freq_in[j] * a);
    __syncthreads();

    float acc = b_h0[j];
#pragma unroll
    for (int i = 0; i < FO; i++) acc = fmaf(hs[i], w_h0[i * FO + j], acc);
    float v = sinf(freq_h0[j] * acc);
    __syncthreads();
    hs[j] = v;
    __syncthreads();

    acc = b_h1[j];
#pragma unroll
    for (int i = 0; i < FO; i++) acc = fmaf(hs[i], w_h1[i * FO + j], acc);
    g_h[l * FO + j] = sinf(freq_h1[j] * acc);
}

// ============================================================================
// Kernel B: k^T[d][l] = (h[l] . w_out[:,d]) * exp(-t*|delta_d|)
// ============================================================================
__global__ void kgemm_kernel(const float* __restrict__ w_out) {
    __shared__ float hs[128][FO];
    __shared__ float ws[FO][32];
    int l0 = blockIdx.x * 128;
    int d0 = blockIdx.y * 32;
    int tid = threadIdx.x;   // 256

    for (int idx = tid; idx < 128 * FO; idx += 256)
        hs[idx >> 6][idx & 63] = g_h[(l0 + (idx >> 6)) * FO + (idx & 63)];
    for (int idx = tid; idx < FO * 32; idx += 256)
        ws[idx >> 5][idx & 31] = w_out[(idx >> 5) * HD + d0 + (idx & 31)];
    __syncthreads();

    int dx = tid & 31, ly = tid >> 5;
    int d = d0 + dx;
    const float ln001 = -4.605170185988091f;
    float mind = ln001 / 1.5f, maxd = ln001 / 0.3f;
    float delta = mind + (maxd - mind) * ((float)d / (float)(HD - 1));
    float ad = fabsf(delta);

    for (int ls = ly; ls < 128; ls += 8) {
        float acc = 0.f;
#pragma unroll
        for (int i = 0; i < FO; i++) acc = fmaf(hs[ls][i], ws[i][dx], acc);
        int l = l0 + ls;
        float t = (float)l * (1.0f / (float)(SEQLEN - 1));
        g_kT[(size_t)d * SEQLEN + l] = acc * expf(-t * ad);
    }
}

// ============================================================================
// Register-blocked FFT core (N2 = 8192 complex, NT = 512 threads), fused
// radix-4 (3-multiply) stages:
//   P1 (stride-256): fused gmem load+m=4096, then (2048,1024), (512,256)
//   P2 (stride-16):  (128,64), (32,16)
//   tail (contig16): (8,4), (2,1)      [constant twiddles]
// Inverse mirrors. Twiddles from gmem tables (L1-cached).
// ============================================================================

template<int D, int STEP>
__device__ __forceinline__ void fwd4(float2* r, int o1, int o2, int pbase) {
#pragma unroll
    for (int jj = 0; jj < D; jj++) {
        int p = pbase + STEP * jj;
        float2 W1 = __ldg(&g_tw[o1 + p]);
        float2 W2 = __ldg(&g_tw[o2 + p]);
        float2 W3 = __ldg(&g_tw3[o1 + p]);
#pragma unroll
        for (int j0 = 0; j0 < 16; j0 += 4 * D) {
            int j = j0 + jj;
            float2 x0 = r[j], x1 = r[j + D], x2 = r[j + 2 * D], x3 = r[j + 3 * D];
            float2 u0 = cadd(x0, x2), u1 = cadd(x1, x3);
            float2 e  = csub(x0, x2), od = csub(x1, x3);
            r[j]         = cadd(u0, u1);
            r[j + D]     = cmul(csub(u0, u1), W2);
            r[j + 2 * D] = cmul(subim(e, od), W1);
            r[j + 3 * D] = cmul(addim(e, od), W3);
        }
    }
}

template<int D, int STEP>
__device__ __forceinline__ void inv4(float2* r, int o1, int o2, int pbase) {
#pragma unroll
    for (int jj = 0; jj < D; jj++) {
        int p = pbase + STEP * jj;
        float2 W1 = __ldg(&g_tw[o1 + p]);
        float2 W2 = __ldg(&g_tw[o2 + p]);
        float2 W3 = __ldg(&g_tw3[o1 + p]);
#pragma unroll
        for (int j0 = 0; j0 < 16; j0 += 4 * D) {
            int j = j0 + jj;
            float2 x0 = r[j], x1 = r[j + D], x2 = r[j + 2 * D], x3 = r[j + 3 * D];
            float2 p1 = cmulc(x1, W2), p2 = cmulc(x2, W1), p3 = cmulc(x3, W3);
            float2 A = cadd(x0, p1), C = csub(x0, p1);
            float2 B = cadd(p2, p3), Dp = csub(p2, p3);
            r[j]         = cadd(A, B);
            r[j + 2 * D] = csub(A, B);
            r[j + D]     = addim(C, Dp);
            r[j + 3 * D] = subim(C, Dp);
        }
    }
}

#define CW1_INIT { make_float2(1.f,0.f), make_float2(0.9238795325112867f,-0.3826834323650898f), \
                   make_float2(0.7071067811865476f,-0.7071067811865476f), make_float2(0.3826834323650898f,-0.9238795325112867f) }
#define CW2_INIT { make_float2(1.f,0.f), make_float2(0.7071067811865476f,-0.7071067811865476f), \
                   make_float2(0.f,-1.f), make_float2(-0.7071067811865476f,-0.7071067811865476f) }
#define CW3_INIT { make_float2(1.f,0.f), make_float2(0.3826834323650898f,-0.9238795325112867f), \
                   make_float2(-0.7071067811865476f,-0.7071067811865476f), make_float2(-0.9238795325112867f,0.3826834323650898f) }

__device__ __forceinline__ void fwd_tail(float2* Z) {
    const float2 CW1[4] = CW1_INIT;
    const float2 CW2[4] = CW2_INIT;
    const float2 CW3[4] = CW3_INIT;
    int base = threadIdx.x * 16, s = threadIdx.x & 15;
    float2 r[16];
#pragma unroll
    for (int o = 0; o < 16; o++) r[o] = Z[base + (o ^ s)];
#pragma unroll
    for (int o = 0; o < 4; o++) {          // stages 8,4
        float2 x0 = r[o], x1 = r[o + 4], x2 = r[o + 8], x3 = r[o + 12];
        float2 u0 = cadd(x0, x2), u1 = cadd(x1, x3);
        float2 e  = csub(x0, x2), od = csub(x1, x3);
        r[o]      = cadd(u0, u1);
        r[o + 4]  = cmul(csub(u0, u1), CW2[o]);
        r[o + 8]  = cmul(subim(e, od), CW1[o]);
        r[o + 12] = cmul(addim(e, od), CW3[o]);
    }
#pragma unroll
    for (int a = 0; a < 16; a += 4) {      // stages 2,1 (twiddle-free)
        float2 x0 = r[a], x1 = r[a + 1], x2 = r[a + 2], x3 = r[a + 3];
        float2 u0 = cadd(x0, x2), u1 = cadd(x1, x3);
        float2 e  = csub(x0, x2), od = csub(x1, x3);
        r[a]     = cadd(u0, u1);
        r[a + 1] = csub(u0, u1);
        r[a + 2] = subim(e, od);
        r[a + 3] = addim(e, od);
    }
#pragma unroll
    for (int o = 0; o < 16; o++) Z[base + (o ^ s)] = r[o];
}

__device__ __forceinline__ void inv_tail(float2* Z) {
    const float2 CW1[4] = CW1_INIT;
    const float2 CW2[4] = CW2_INIT;
    const float2 CW3[4] = CW3_INIT;
    int base = threadIdx.x * 16, s = threadIdx.x & 15;
    float2 r[16];
#pragma unroll
    for (int o = 0; o < 16; o++) r[o] = Z[base + (o ^ s)];
#pragma unroll
    for (int a = 0; a < 16; a += 4) {      // stages 1,2 (twiddle-free)
        float2 x0 = r[a], x1 = r[a + 1], x2 = r[a + 2], x3 = r[a + 3];
        float2 a0 = cadd(x0, x1), a1 = csub(x0, x1);
        float2 a2 = cadd(x2, x3), a3 = csub(x2, x3);
        r[a]     = cadd(a0, a2);
        r[a + 2] = csub(a0, a2);
        r[a + 1] = addim(a1, a3);
        r[a + 3] = subim(a1, a3);
    }
#pragma unroll
    for (int o = 0; o < 4; o++) {          // stages 4,8
        float2 x0 = r[o], x1 = r[o + 4], x2 = r[o + 8], x3 = r[o + 12];
        float2 p1 = cmulc(x1, CW2[o]), p2 = cmulc(x2, CW1[o]), p3 = cmulc(x3, CW3[o]);
        float2 A = cadd(x0, p1), C = csub(x0, p1);
        float2 B = cadd(p2, p3), Dp = csub(p2, p3);
        r[o]      = cadd(A, B);
        r[o + 8]  = csub(A, B);
        r[o + 4]  = addim(C, Dp);
        r[o + 12] = subim(C, Dp);
    }
#pragma unroll
    for (int o = 0; o < 16; o++) Z[base + (o ^ s)] = r[o];
}

__device__ __forceinline__ void fft_fwd_8k(float2* Z, const float2* __restrict__ src) {
    int t = threadIdx.x;
    float2 r[16];
    {
        int h = t >> 8, c = t & 255;
        if (h == 0) {
#pragma unroll
            for (int j = 0; j < 16; j++) r[j] = src[c + 256 * j];
        } else {
#pragma unroll
            for (int j = 0; j < 16; j++) {
                float2 v = src[c + 256 * j];
                r[j] = cmul(v, __ldg(&g_tw[c + 256 * j]));   // fused zero-pad stage m=4096
            }
        }
        fwd4<4, 256>(r, 4096, 6144, c);   // stages 2048,1024
        fwd4<1, 256>(r, 7168, 7680, c);   // stages 512,256
        int base = h * 4096 + c;
#pragma unroll
        for (int j = 0; j < 16; j++) Z[base + 256 * j] = r[j];
    }
    __syncthreads();
    {
        int ql = t & 15, g = t >> 4;
        int base = ql + 256 * g;
#pragma unroll
        for (int j = 0; j < 16; j++) r[j] = Z[base + 16 * j];
        __syncthreads();                  // all reads done before swizzled writes
        fwd4<4, 16>(r, 7936, 8064, ql);  // stages 128,64
        fwd4<1, 16>(r, 8128, 8160, ql);  // stages 32,16
#pragma unroll
        for (int j = 0; j < 16; j++) Z[(ql ^ j) + 16 * j + 256 * g] = r[j];
    }
    __syncthreads();
    fwd_tail(Z);                          // stages 8..1
}

__device__ __forceinline__ void fft_inv_8k(float2* Z) {
    int t = threadIdx.x;
    inv_tail(Z);                          // stages 1..8
    __syncthreads();
    float2 r[16];
    {
        int ql = t & 15, g = t >> 4;
#pragma unroll
        for (int j = 0; j < 16; j++) r[j] = Z[(ql ^ j) + 16 * j + 256 * g];
        __syncthreads();                  // all swizzled reads before plain writes
        inv4<1, 16>(r, 8128, 8160, ql);  // stages 16,32
        inv4<4, 16>(r, 7936, 8064, ql);  // stages 64,128
        int base = ql + 256 * g;
#pragma unroll
        for (int j = 0; j < 16; j++) Z[base + 16 * j] = r[j];
    }
    __syncthreads();
    {
        int h = t >> 8, c = t & 255;
        int base = h * 4096 + c;
#pragma unroll
        for (int j = 0; j < 16; j++) r[j] = Z[base + 256 * j];
        inv4<1, 256>(r, 7168, 7680, c);  // stages 256,512
        inv4<4, 256>(r, 4096, 6144, c);  // stages 1024,2048
#pragma unroll
        for (int j = 0; j < 16; j++) Z[base + 256 * j] = r[j];
    }
    __syncthreads();
}

__device__ __forceinline__ int brev13(int k) {
    return (int)(__brev((unsigned)k) >> 19);
}

// ============================================================================
// Kernel C: filter spectrum, permuted storage.  One CTA per d.
// ============================================================================
__global__ void __launch_bounds__(NT, 2) kfft_kernel() {
    extern __shared__ float2 sm[];
    float2* Z = sm;                       // 8192 float2 = 64 KB
    int d = blockIdx.x, tid = threadIdx.x;

    fft_fwd_8k(Z, (const float2*)(g_kT + (size_t)d * SEQLEN));
    __syncthreads();

    const float invN = 1.0f / (float)NFFT;
    float2* K1 = g_Kfp1 + (size_t)d * 4097;
    float2* K2 = g_Kfp2 + (size_t)d * 4097;
#pragma unroll
    for (int it = 0; it < 8; it++) {
        int idx = tid + it * NT;
        int k = ((idx & 31) << 7) | (idx >> 5);
        if (idx == 0) {
            float2 A = Z[0];
            K1[0] = make_float2((A.x + A.y) * invN, 0.f);
            K2[0] = make_float2((A.x - A.y) * invN, 0.f);
            float2 A1 = Z[1];                      // brev13(4096)=1, swz(1)=1
            K1[4096] = make_float2(A1.x * invN, -A1.y * invN);
            K2[4096] = make_float2(0.f, 0.f);
        } else {
            int j = 8192 - k;
            float2 A  = Z[swz(brev13(k))];
            float2 Bv = Z[swz(brev13(j))];
            float2 Fe = make_float2(0.5f * (A.x + Bv.x), 0.5f * (A.y - Bv.y));
            float dx = A.x - Bv.x, dy = A.y + Bv.y;
            float2 Fo = make_float2(0.5f * dy, -0.5f * dx);
            float2 W = __ldg(&g_wkp[idx]);
            float c = W.x, s = W.y;
            float2 WFo = make_float2(c * Fo.x - s * Fo.y, c * Fo.y + s * Fo.x);
            K1[idx] = make_float2((Fe.x + WFo.x) * invN,  (Fe.y + WFo.y) * invN);
            K2[idx] = make_float2((Fe.x - WFo.x) * invN, -(Fe.y - WFo.y) * invN);
        }
    }
}

// ============================================================================
// Transposes
// ============================================================================
__global__ void transpose_in(const float* __restrict__ x) {
    __shared__ float tile[32][33];
    int b = blockIdx.z;
    int l0 = blockIdx.x << 5, d0 = blockIdx.y << 5;
    int tx = threadIdx.x, ty = threadIdx.y;
#pragma unroll
    for (int r = 0; r < 4; r++) {
        int l = l0 + ty + r * 8;
        tile[ty + r * 8][tx] = x[((size_t)b * SEQLEN + l) * HD + d0 + tx];
    }
    __syncthreads();
#pragma unroll
    for (int r = 0; r < 4; r++) {
        int d = d0 + ty + r * 8;
        g_xT[((size_t)b * HD + d) * SEQLEN + l0 + tx] = tile[tx][ty + r * 8];
    }
}

__global__ void transpose_out(float* __restrict__ out) {
    __shared__ float tile[32][33];
    int b = blockIdx.z;
    int l0 = blockIdx.x << 5, d0 = blockIdx.y << 5;
    int tx = threadIdx.x, ty = threadIdx.y;
#pragma unroll
    for (int r = 0; r < 4; r++) {
        int d = d0 + ty + r * 8;
        tile[ty + r * 8][tx] = g_xT[((size_t)b * HD + d) * SEQLEN + l0 + tx];
    }
    __syncthreads();
#pragma unroll
    for (int r = 0; r < 4; r++) {
        int l = l0 + ty + r * 8;
        out[((size_t)b * SEQLEN + l) * HD + d0 + tx] = tile[tx][ty + r * 8];
    }
}

// ============================================================================
// Kernel D: per-channel FFT convolution, in-place on xT row.
// ============================================================================
__global__ void __launch_bounds__(NT, 2) fftconv_kernel(const float* __restrict__ bias) {
    extern __shared__ float2 sm[];
    float2* Z = sm;                       // 8192 float2 = 64 KB
    int bd = blockIdx.x, tid = threadIdx.x;
    int d = bd % HD;

    float2* xrow = (float2*)(g_xT + (size_t)bd * SEQLEN);
    fft_fwd_8k(Z, xrow);
    __syncthreads();

    // unpack -> X[k], multiply by Kf, repack (bit-reversed, swizzled, remapped)
    const float2* K1 = g_Kfp1 + (size_t)d * 4097;
    const float2* K2 = g_Kfp2 + (size_t)d * 4097;
#pragma unroll
    for (int it = 0; it < 8; it++) {
        int idx = tid + it * NT;
        int k = ((idx & 31) << 7) | (idx >> 5);
        if (idx == 0) {
            // k = 0 (DC + Nyquist of the 16384-FFT, packed)
            float2 A = Z[0];
            float X0 = A.x + A.y, XN = A.x - A.y;
            float2 K0 = K1[0], KN = K2[0];
            float2 Y0 = make_float2(X0 * K0.x, X0 * K0.y);
            float2 YN = make_float2(XN * KN.x, XN * KN.y);
            float2 Ge = make_float2(0.5f * (Y0.x + YN.x), 0.5f * (Y0.y - YN.y));
            float2 Go = make_float2(0.5f * (Y0.x - YN.x), 0.5f * (Y0.y + YN.y));
            Z[0] = make_float2(Ge.x - Go.y, Ge.y + Go.x);
            // k = 4096 (self-paired): X = conj(Z[1]); Z[1] = conj(X*K)
            float2 A1 = Z[1];
            float2 Kq = K1[4096];
            float2 X = make_float2(A1.x, -A1.y);
            float2 Y = cmul(X, Kq);
            Z[1] = make_float2(Y.x, -Y.y);
        } else {
            int j = 8192 - k;
            int ra = swz(brev13(k));
            int rb = swz(brev13(j));
            float2 A  = Z[ra];
            float2 Bv = Z[rb];
            float2 Fe = make_float2(0.5f * (A.x + Bv.x), 0.5f * (A.y - Bv.y));
            float dx = A.x - Bv.x, dy = A.y + Bv.y;
            float2 Fo = make_float2(0.5f * dy, -0.5f * dx);
            float2 W = __ldg(&g_wkp[idx]);
            float c = W.x, s = W.y;
            float2 WFo = make_float2(c * Fo.x - s * Fo.y, c * Fo.y + s * Fo.x);
            float2 Xk = make_float2(Fe.x + WFo.x,  Fe.y + WFo.y);
            float2 Xj = make_float2(Fe.x - WFo.x, -(Fe.y - WFo.y));
            float2 Kk = K1[idx], Kj = K2[idx];
            float2 Yk = cmul(Xk, Kk), Yj = cmul(Xj, Kj);
            float2 Ge = make_float2(0.5f * (Yk.x + Yj.x), 0.5f * (Yk.y - Yj.y));
            float2 Gd = make_float2(0.5f * (Yk.x - Yj.x), 0.5f * (Yk.y + Yj.y));
            float2 Go = make_float2(c * Gd.x + s * Gd.y, c * Gd.y - s * Gd.x);
            Z[ra] = make_float2(Ge.x - Go.y, Ge.y + Go.x);
            Z[rb] = make_float2(Ge.x + Go.y, Go.x - Ge.y);
        }
    }
    __syncthreads();

    fft_inv_8k(Z);                        // leaves plain layout, synced

    // final inverse stage m=4096 fused with store (first half only), plain layout
    float bv = bias[d];
    const float scl = 1.0f / (float)N2;
#pragma unroll
    for (int it = 0; it < 8; it++) {
        int i = tid + it * NT;
        float2 w = __ldg(&g_tw[i]);
        float2 zb = Z[i + 4096];
        float tx = zb.x * w.x + zb.y * w.y;
        float ty = zb.y * w.x - zb.x * w.y;
        float2 za = Z[i];
        xrow[i] = make_float2(fmaf(za.x + tx, scl, bv), fmaf(za.y + ty, scl, bv));
    }
}

// ============================================================================
// launch — transpose_in forked onto a second stream so it overlaps the
// filter chain (twfill -> mlp -> kgemm -> kfft). Captured fork/join via events.
// ============================================================================
extern "C" void kernel_launch(void* const* d_in, const int* in_sizes, int n_in,
                              void* d_out, int out_size) {
    (void)in_sizes; (void)n_in; (void)out_size;
    const float* x       = (const float*)d_in[0];
    const float* w_in    = (const float*)d_in[1];
    const float* b_in    = (const float*)d_in[2];
    const float* freq_in = (const float*)d_in[3];
    const float* w_h0    = (const float*)d_in[4];
    const float* b_h0    = (const float*)d_in[5];
    const float* freq_h0 = (const float*)d_in[6];
    const float* w_h1    = (const float*)d_in[7];
    const float* b_h1    = (const float*)d_in[8];
    const float* freq_h1 = (const float*)d_in[9];
    const float* w_out   = (const float*)d_in[10];
    const float* bias    = (const float*)d_in[11];
    float* out = (float*)d_out;

    const int smemBytes = 8192 * sizeof(float2);   // 64 KB (Z only)
    cudaFuncSetAttribute(kfft_kernel,    cudaFuncAttributeMaxDynamicSharedMemorySize, smemBytes);
    cudaFuncSetAttribute(fftconv_kernel, cudaFuncAttributeMaxDynamicSharedMemorySize, smemBytes);

    cudaStream_t s2;
    cudaEvent_t evFork, evJoin;
    cudaStreamCreateWithFlags(&s2, cudaStreamNonBlocking);
    cudaEventCreateWithFlags(&evFork, cudaEventDisableTiming);
    cudaEventCreateWithFlags(&evJoin, cudaEventDisableTiming);

    // fork: transpose_in on s2
    cudaEventRecord(evFork, 0);
    cudaStreamWaitEvent(s2, evFork, 0);
    transpose_in<<<dim3(SEQLEN / 32, HD / 32, NB), dim3(32, 8), 0, s2>>>(x);
    cudaEventRecord(evJoin, s2);

    // filter chain on the main (capture) stream
    twfill_kernel<<<32, 256>>>();
    mlp_kernel<<<SEQLEN, FO>>>(w_in, b_in, freq_in, w_h0, b_h0, freq_h0, w_h1, b_h1, freq_h1);
    kgemm_kernel<<<dim3(SEQLEN / 128, HD / 32), 256>>>(w_out);
    kfft_kernel<<<HD, NT, smemBytes>>>();

    // join, then convolution + output transpose
    cudaStreamWaitEvent(0, evJoin, 0);
    fftconv_kernel<<<NB * HD, NT, smemBytes>>>(bias);
    transpose_out<<<dim3(SEQLEN / 32, HD / 32, NB), dim3(32, 8)>>>(out);

    cudaEventDestroy(evFork);
    cudaEventDestroy(evJoin);
    cudaStreamDestroy(s2);
}

// round 13
// speedup vs baseline: 2.9596x; 1.0561x over previous
#include <cuda_runtime.h>
#include <cuda_bf16.h>
#include <math.h>

// ---------------- problem constants ----------------
#define SEQLEN   8192
#define HD       768
#define NB       8
#define FO       64
#define N2       8192
#define NFFT     16384
#define NT       512

// ---------------- device scratch ----------------
__device__ float  g_h   [SEQLEN * FO];
__device__ float  g_kT  [HD * SEQLEN];
__device__ float2 g_Kfp1[HD * 4097];                  // Kf[remap(idx)]
__device__ float2 g_Kfp2[HD * 4097];                  // Kf[8192-remap(idx)]
__device__ float  g_xT  [(size_t)NB * HD * SEQLEN];   // x transposed; y in-place
__device__ float2 g_tw  [N2];                         // per-stage contiguous twiddles e^{-i pi p/m}
__device__ float2 g_tw3 [N2];                         // e^{-i 3 pi p/m}, same layout
__device__ float2 g_wkp [4096];                       // W(remap(idx)) = e^{-i pi k/8192}

// ---------------- helpers ----------------
__device__ __forceinline__ int swz(int i) { return i ^ ((i >> 4) & 15); }
__device__ __forceinline__ float2 cadd(float2 a, float2 b) { return make_float2(a.x + b.x, a.y + b.y); }
__device__ __forceinline__ float2 csub(float2 a, float2 b) { return make_float2(a.x - b.x, a.y - b.y); }
__device__ __forceinline__ float2 addim(float2 a, float2 b) { return make_float2(a.x - b.y, a.y + b.x); } // a + i*b
__device__ __forceinline__ float2 subim(float2 a, float2 b) { return make_float2(a.x + b.y, a.y - b.x); } // a - i*b
__device__ __forceinline__ float2 cmul(float2 a, float2 b) {
    return make_float2(a.x * b.x - a.y * b.y, a.x * b.y + a.y * b.x);
}
__device__ __forceinline__ float2 cmulc(float2 a, float2 b) {   // a * conj(b)
    return make_float2(a.x * b.x + a.y * b.y, a.y * b.x - a.x * b.y);
}

// ============================================================================
// Twiddle tables (gmem, once) — parallel fill, flat index -> (m, p) via clz
// ============================================================================
__global__ void twfill_kernel() {     // grid 32, block 256
    int gid = blockIdx.x * 256 + threadIdx.x;     // 0..8191
    if (gid == 8191) {
        g_tw[8191]  = make_float2(1.f, 0.f);
        g_tw3[8191] = make_float2(1.f, 0.f);
    } else {
        unsigned u = 8192u - (unsigned)gid;       // u in [2, 8192]
        int m = 1 << (31 - __clz(u - 1));         // m < u <= 2m
        int p = 2 * m - (int)u;
        float invm = 1.0f / (float)m;
        float s, c;
        sincospif(-(float)p * invm, &s, &c);
        g_tw[gid] = make_float2(c, s);
        sincospif(-3.0f * (float)p * invm, &s, &c);
        g_tw3[gid] = make_float2(c, s);
    }
    if (gid < 4096) {
        int k = ((gid & 31) << 7) | (gid >> 5);
        float s, c;
        sincospif(-(float)k * (1.0f / 8192.0f), &s, &c);
        g_wkp[gid] = make_float2(c, s);
    }
}

// ============================================================================
// Kernel A: implicit filter MLP
// ============================================================================
__global__ void mlp_kernel(const float* __restrict__ w_in, const float* __restrict__ b_in,
                           const float* __restrict__ freq_in,
                           const float* __restrict__ w_h0, const float* __restrict__ b_h0,
                           const float* __restrict__ freq_h0,
                           const float* __restrict__ w_h1, const float* __restrict__ b_h1,
                           const float* __restrict__ freq_h1) {
    __shared__ float hs[FO];
    int l = blockIdx.x;
    int j = threadIdx.x;

    float t   = (float)l * (1.0f / (float)(SEQLEN - 1));
    float wan = 6.283185307179586f * (float)l / (float)SEQLEN;
    float ph  = 1e-4f * wan;
    float z0 = t, z1 = cosf(ph), z2 = -sinf(ph);

    float a = fmaf(z0, w_in[j], fmaf(z1, w_in[FO + j], fmaf(z2, w_in[2 * FO + j], b_in[j])));
    hs[j] = sinf(freq_in[j] * a);
    __syncthreads();

    float acc = b_h0[j];
#pragma unroll
    for (int i = 0; i < FO; i++) acc = fmaf(hs[i], w_h0[i * FO + j], acc);
    float v = sinf(freq_h0[j] * acc);
    __syncthreads();
    hs[j] = v;
    __syncthreads();

    acc = b_h1[j];
#pragma unroll
    for (int i = 0; i < FO; i++) acc = fmaf(hs[i], w_h1[i * FO + j], acc);
    g_h[l * FO + j] = sinf(freq_h1[j] * acc);
}

// ============================================================================
// Kernel B: k^T[d][l] = (h[l] . w_out[:,d]) * exp(-t*|delta_d|)
//  - lanes vary l  -> coalesced g_kT stores
//  - hsT[64][129]  -> conflict-free transpose + stride-1 reads
//  - 4x4 register tile: 8 LDS per 16 FMA
//  - decay via expf recurrence: 8 expf/thread
// ============================================================================
__global__ void kgemm_kernel(const float* __restrict__ w_out) {
    __shared__ float hsT[FO][129];
    __shared__ float ws[FO][32];
    int l0 = blockIdx.x * 128;
    int d0 = blockIdx.y * 32;
    int tid = threadIdx.x;   // 256

    for (int idx = tid; idx < 128 * FO; idx += 256) {
        int row = idx >> 6, i = idx & 63;
        hsT[i][row] = g_h[(l0 + row) * FO + i];
    }
    for (int idx = tid; idx < FO * 32; idx += 256)
        ws[idx >> 5][idx & 31] = w_out[(idx >> 5) * HD + d0 + (idx & 31)];
    __syncthreads();

    int lx = tid & 31, dy = tid >> 5;    // lanes vary l; dy in 0..7
    float acc[4][4] = {};
#pragma unroll 8
    for (int i = 0; i < FO; i++) {
        float h[4], w[4];
#pragma unroll
        for (int q = 0; q < 4; q++) h[q] = hsT[i][lx + 32 * q];
#pragma unroll
        for (int r = 0; r < 4; r++) w[r] = ws[i][dy + 8 * r];
#pragma unroll
        for (int q = 0; q < 4; q++)
#pragma unroll
            for (int r = 0; r < 4; r++)
                acc[q][r] = fmaf(h[q], w[r], acc[q][r]);
    }

    const float ln001 = -4.605170185988091f;
    const float mind = ln001 / 1.5f, maxd = ln001 / 0.3f;
#pragma unroll
    for (int r = 0; r < 4; r++) {
        int d = d0 + dy + 8 * r;
        float delta = mind + (maxd - mind) * ((float)d / (float)(HD - 1));
        float cr = fabsf(delta) * (1.0f / (float)(SEQLEN - 1));
        float e = expf(-(float)(l0 + lx) * cr);   // decay at q=0
        float s = expf(-32.0f * cr);              // step factor per q
        float* dst = g_kT + (size_t)d * SEQLEN + l0 + lx;
#pragma unroll
        for (int q = 0; q < 4; q++) {
            dst[32 * q] = acc[q][r] * e;
            e *= s;
        }
    }
}

// ============================================================================
// Register-blocked FFT core (N2 = 8192 complex, NT = 512 threads), fused
// radix-4 (3-multiply) stages. Twiddles from gmem tables (L1-cached).
// ============================================================================

template<int D, int STEP>
__device__ __forceinline__ void fwd4(float2* r, int o1, int o2, int pbase) {
#pragma unroll
    for (int jj = 0; jj < D; jj++) {
        int p = pbase + STEP * jj;
        float2 W1 = __ldg(&g_tw[o1 + p]);
        float2 W2 = __ldg(&g_tw[o2 + p]);
        float2 W3 = __ldg(&g_tw3[o1 + p]);
#pragma unroll
        for (int j0 = 0; j0 < 16; j0 += 4 * D) {
            int j = j0 + jj;
            float2 x0 = r[j], x1 = r[j + D], x2 = r[j + 2 * D], x3 = r[j + 3 * D];
            float2 u0 = cadd(x0, x2), u1 = cadd(x1, x3);
            float2 e  = csub(x0, x2), od = csub(x1, x3);
            r[j]         = cadd(u0, u1);
            r[j + D]     = cmul(csub(u0, u1), W2);
            r[j + 2 * D] = cmul(subim(e, od), W1);
            r[j + 3 * D] = cmul(addim(e, od), W3);
        }
    }
}

template<int D, int STEP>
__device__ __forceinline__ void inv4(float2* r, int o1, int o2, int pbase) {
#pragma unroll
    for (int jj = 0; jj < D; jj++) {
        int p = pbase + STEP * jj;
        float2 W1 = __ldg(&g_tw[o1 + p]);
        float2 W2 = __ldg(&g_tw[o2 + p]);
        float2 W3 = __ldg(&g_tw3[o1 + p]);
#pragma unroll
        for (int j0 = 0; j0 < 16; j0 += 4 * D) {
            int j = j0 + jj;
            float2 x0 = r[j], x1 = r[j + D], x2 = r[j + 2 * D], x3 = r[j + 3 * D];
            float2 p1 = cmulc(x1, W2), p2 = cmulc(x2, W1), p3 = cmulc(x3, W3);
            float2 A = cadd(x0, p1), C = csub(x0, p1);
            float2 B = cadd(p2, p3), Dp = csub(p2, p3);
            r[j]         = cadd(A, B);
            r[j + 2 * D] = csub(A, B);
            r[j + D]     = addim(C, Dp);
            r[j + 3 * D] = subim(C, Dp);
        }
    }
}

#define CW1_INIT { make_float2(1.f,0.f), make_float2(0.9238795325112867f,-0.3826834323650898f), \
                   make_float2(0.7071067811865476f,-0.7071067811865476f), make_float2(0.3826834323650898f,-0.9238795325112867f) }
#define CW2_INIT { make_float2(1.f,0.f), make_float2(0.7071067811865476f,-0.7071067811865476f), \
                   make_float2(0.f,-1.f), make_float2(-0.7071067811865476f,-0.7071067811865476f) }
#define CW3_INIT { make_float2(1.f,0.f), make_float2(0.3826834323650898f,-0.9238795325112867f), \
                   make_float2(-0.7071067811865476f,-0.7071067811865476f), make_float2(-0.9238795325112867f,0.3826834323650898f) }

__device__ __forceinline__ void fwd_tail(float2* Z) {
    const float2 CW1[4] = CW1_INIT;
    const float2 CW2[4] = CW2_INIT;
    const float2 CW3[4] = CW3_INIT;
    int base = threadIdx.x * 16, s = threadIdx.x & 15;
    float2 r[16];
#pragma unroll
    for (int o = 0; o < 16; o++) r[o] = Z[base + (o ^ s)];
#pragma unroll
    for (int o = 0; o < 4; o++) {          // stages 8,4
        float2 x0 = r[o], x1 = r[o + 4], x2 = r[o + 8], x3 = r[o + 12];
        float2 u0 = cadd(x0, x2), u1 = cadd(x1, x3);
        float2 e  = csub(x0, x2), od = csub(x1, x3);
        r[o]      = cadd(u0, u1);
        r[o + 4]  = cmul(csub(u0, u1), CW2[o]);
        r[o + 8]  = cmul(subim(e, od), CW1[o]);
        r[o + 12] = cmul(addim(e, od), CW3[o]);
    }
#pragma unroll
    for (int a = 0; a < 16; a += 4) {      // stages 2,1 (twiddle-free)
        float2 x0 = r[a], x1 = r[a + 1], x2 = r[a + 2], x3 = r[a + 3];
        float2 u0 = cadd(x0, x2), u1 = cadd(x1, x3);
        float2 e  = csub(x0, x2), od = csub(x1, x3);
        r[a]     = cadd(u0, u1);
        r[a + 1] = csub(u0, u1);
        r[a + 2] = subim(e, od);
        r[a + 3] = addim(e, od);
    }
#pragma unroll
    for (int o = 0; o < 16; o++) Z[base + (o ^ s)] = r[o];
}

__device__ __forceinline__ void inv_tail(float2* Z) {
    const float2 CW1[4] = CW1_INIT;
    const float2 CW2[4] = CW2_INIT;
    const float2 CW3[4] = CW3_INIT;
    int base = threadIdx.x * 16, s = threadIdx.x & 15;
    float2 r[16];
#pragma unroll
    for (int o = 0; o < 16; o++) r[o] = Z[base + (o ^ s)];
#pragma unroll
    for (int a = 0; a < 16; a += 4) {      // stages 1,2 (twiddle-free)
        float2 x0 = r[a], x1 = r[a + 1], x2 = r[a + 2], x3 = r[a + 3];
        float2 a0 = cadd(x0, x1), a1 = csub(x0, x1);
        float2 a2 = cadd(x2, x3), a3 = csub(x2, x3);
        r[a]     = cadd(a0, a2);
        r[a + 2] = csub(a0, a2);
        r[a + 1] = addim(a1, a3);
        r[a + 3] = subim(a1, a3);
    }
#pragma unroll
    for (int o = 0; o < 4; o++) {          // stages 4,8
        float2 x0 = r[o], x1 = r[o + 4], x2 = r[o + 8], x3 = r[o + 12];
        float2 p1 = cmulc(x1, CW2[o]), p2 = cmulc(x2, CW1[o]), p3 = cmulc(x3, CW3[o]);
        float2 A = cadd(x0, p1), C = csub(x0, p1);
        float2 B = cadd(p2, p3), Dp = csub(p2, p3);
        r[o]      = cadd(A, B);
        r[o + 8]  = csub(A, B);
        r[o + 4]  = addim(C, Dp);
        r[o + 12] = subim(C, Dp);
    }
#pragma unroll
    for (int o = 0; o < 16; o++) Z[base + (o ^ s)] = r[o];
}

__device__ __forceinline__ void fft_fwd_8k(float2* Z, const float2* __restrict__ src) {
    int t = threadIdx.x;
    float2 r[16];
    {
        int h = t >> 8, c = t & 255;
        if (h == 0) {
#pragma unroll
            for (int j = 0; j < 16; j++) r[j] = src[c + 256 * j];
        } else {
#pragma unroll
            for (int j = 0; j < 16; j++) {
                float2 v = src[c + 256 * j];
                r[j] = cmul(v, __ldg(&g_tw[c + 256 * j]));   // fused zero-pad stage m=4096
            }
        }
        fwd4<4, 256>(r, 4096, 6144, c);   // stages 2048,1024
        fwd4<1, 256>(r, 7168, 7680, c);   // stages 512,256
        int base = h * 4096 + c;
#pragma unroll
        for (int j = 0; j < 16; j++) Z[base + 256 * j] = r[j];
    }
    __syncthreads();
    {
        int ql = t & 15, g = t >> 4;
        int base = ql + 256 * g;
#pragma unroll
        for (int j = 0; j < 16; j++) r[j] = Z[base + 16 * j];
        __syncthreads();                  // all reads done before swizzled writes
        fwd4<4, 16>(r, 7936, 8064, ql);  // stages 128,64
        fwd4<1, 16>(r, 8128, 8160, ql);  // stages 32,16
#pragma unroll
        for (int j = 0; j < 16; j++) Z[(ql ^ j) + 16 * j + 256 * g] = r[j];
    }
    __syncthreads();
    fwd_tail(Z);                          // stages 8..1
}

__device__ __forceinline__ void fft_inv_8k(float2* Z) {
    int t = threadIdx.x;
    inv_tail(Z);                          // stages 1..8
    __syncthreads();
    float2 r[16];
    {
        int ql = t & 15, g = t >> 4;
#pragma unroll
        for (int j = 0; j < 16; j++) r[j] = Z[(ql ^ j) + 16 * j + 256 * g];
        __syncthreads();                  // all swizzled reads before plain writes
        inv4<1, 16>(r, 8128, 8160, ql);  // stages 16,32
        inv4<4, 16>(r, 7936, 8064, ql);  // stages 64,128
        int base = ql + 256 * g;
#pragma unroll
        for (int j = 0; j < 16; j++) Z[base + 16 * j] = r[j];
    }
    __syncthreads();
    {
        int h = t >> 8, c = t & 255;
        int base = h * 4096 + c;
#pragma unroll
        for (int j = 0; j < 16; j++) r[j] = Z[base + 256 * j];
        inv4<1, 256>(r, 7168, 7680, c);  // stages 256,512
        inv4<4, 256>(r, 4096, 6144, c);  // stages 1024,2048
#pragma unroll
        for (int j = 0; j < 16; j++) Z[base + 256 * j] = r[j];
    }
    __syncthreads();
}

__device__ __forceinline__ int brev13(int k) {
    return (int)(__brev((unsigned)k) >> 19);
}

// ============================================================================
// Kernel C: filter spectrum, permuted storage.  One CTA per d.
// ============================================================================
__global__ void __launch_bounds__(NT, 2) kfft_kernel() {
    extern __shared__ float2 sm[];
    float2* Z = sm;                       // 8192 float2 = 64 KB
    int d = blockIdx.x, tid = threadIdx.x;

    fft_fwd_8k(Z, (const float2*)(g_kT + (size_t)d * SEQLEN));
    __syncthreads();

    const float invN = 1.0f / (float)NFFT;
    float2* K1 = g_Kfp1 + (size_t)d * 4097;
    float2* K2 = g_Kfp2 + (size_t)d * 4097;
#pragma unroll
    for (int it = 0; it < 8; it++) {
        int idx = tid + it * NT;
        int k = ((idx & 31) << 7) | (idx >> 5);
        if (idx == 0) {
            float2 A = Z[0];
            K1[0] = make_float2((A.x + A.y) * invN, 0.f);
            K2[0] = make_float2((A.x - A.y) * invN, 0.f);
            float2 A1 = Z[1];                      // brev13(4096)=1, swz(1)=1
            K1[4096] = make_float2(A1.x * invN, -A1.y * invN);
            K2[4096] = make_float2(0.f, 0.f);
        } else {
            int j = 8192 - k;
            float2 A  = Z[swz(brev13(k))];
            float2 Bv = Z[swz(brev13(j))];
            float2 Fe = make_float2(0.5f * (A.x + Bv.x), 0.5f * (A.y - Bv.y));
            float dx = A.x - Bv.x, dy = A.y + Bv.y;
            float2 Fo = make_float2(0.5f * dy, -0.5f * dx);
            float2 W = __ldg(&g_wkp[idx]);
            float c = W.x, s = W.y;
            float2 WFo = make_float2(c * Fo.x - s * Fo.y, c * Fo.y + s * Fo.x);
            K1[idx] = make_float2((Fe.x + WFo.x) * invN,  (Fe.y + WFo.y) * invN);
            K2[idx] = make_float2((Fe.x - WFo.x) * invN, -(Fe.y - WFo.y) * invN);
        }
    }
}

// ============================================================================
// Transposes
// ============================================================================
__global__ void transpose_in(const float* __restrict__ x) {
    __shared__ float tile[32][33];
    int b = blockIdx.z;
    int l0 = blockIdx.x << 5, d0 = blockIdx.y << 5;
    int tx = threadIdx.x, ty = threadIdx.y;
#pragma unroll
    for (int r = 0; r < 4; r++) {
        int l = l0 + ty + r * 8;
        tile[ty + r * 8][tx] = x[((size_t)b * SEQLEN + l) * HD + d0 + tx];
    }
    __syncthreads();
#pragma unroll
    for (int r = 0; r < 4; r++) {
        int d = d0 + ty + r * 8;
        g_xT[((size_t)b * HD + d) * SEQLEN + l0 + tx] = tile[tx][ty + r * 8];
    }
}

__global__ void transpose_out(float* __restrict__ out) {
    __shared__ float tile[32][33];
    int b = blockIdx.z;
    int l0 = blockIdx.x << 5, d0 = blockIdx.y << 5;
    int tx = threadIdx.x, ty = threadIdx.y;
#pragma unroll
    for (int r = 0; r < 4; r++) {
        int d = d0 + ty + r * 8;
        tile[ty + r * 8][tx] = g_xT[((size_t)b * HD + d) * SEQLEN + l0 + tx];
    }
    __syncthreads();
#pragma unroll
    for (int r = 0; r < 4; r++) {
        int l = l0 + ty + r * 8;
        out[((size_t)b * SEQLEN + l) * HD + d0 + tx] = tile[tx][ty + r * 8];
    }
}

// ============================================================================
// Kernel D: per-channel FFT convolution, in-place on xT row.
// ============================================================================
__global__ void __launch_bounds__(NT, 2) fftconv_kernel(const float* __restrict__ bias) {
    extern __shared__ float2 sm[];
    float2* Z = sm;                       // 8192 float2 = 64 KB
    int bd = blockIdx.x, tid = threadIdx.x;
    int d = bd % HD;

    float2* xrow = (float2*)(g_xT + (size_t)bd * SEQLEN);
    fft_fwd_8k(Z, xrow);
    __syncthreads();

    // unpack -> X[k], multiply by Kf, repack (bit-reversed, swizzled, remapped)
    const float2* K1 = g_Kfp1 + (size_t)d * 4097;
    const float2* K2 = g_Kfp2 + (size_t)d * 4097;
#pragma unroll
    for (int it = 0; it < 8; it++) {
        int idx = tid + it * NT;
        int k = ((idx & 31) << 7) | (idx >> 5);
        if (idx == 0) {
            // k = 0 (DC + Nyquist of the 16384-FFT, packed)
            float2 A = Z[0];
            float X0 = A.x + A.y, XN = A.x - A.y;
            float2 K0 = K1[0], KN = K2[0];
            float2 Y0 = make_float2(X0 * K0.x, X0 * K0.y);
            float2 YN = make_float2(XN * KN.x, XN * KN.y);
            float2 Ge = make_float2(0.5f * (Y0.x + YN.x), 0.5f * (Y0.y - YN.y));
            float2 Go = make_float2(0.5f * (Y0.x - YN.x), 0.5f * (Y0.y + YN.y));
            Z[0] = make_float2(Ge.x - Go.y, Ge.y + Go.x);
            // k = 4096 (self-paired): X = conj(Z[1]); Z[1] = conj(X*K)
            float2 A1 = Z[1];
            float2 Kq = K1[4096];
            float2 X = make_float2(A1.x, -A1.y);
            float2 Y = cmul(X, Kq);
            Z[1] = make_float2(Y.x, -Y.y);
        } else {
            int j = 8192 - k;
            int ra = swz(brev13(k));
            int rb = swz(brev13(j));
            float2 A  = Z[ra];
            float2 Bv = Z[rb];
            float2 Fe = make_float2(0.5f * (A.x + Bv.x), 0.5f * (A.y - Bv.y));
            float dx = A.x - Bv.x, dy = A.y + Bv.y;
            float2 Fo = make_float2(0.5f * dy, -0.5f * dx);
            float2 W = __ldg(&g_wkp[idx]);
            float c = W.x, s = W.y;
            float2 WFo = make_float2(c * Fo.x - s * Fo.y, c * Fo.y + s * Fo.x);
            float2 Xk = make_float2(Fe.x + WFo.x,  Fe.y + WFo.y);
            float2 Xj = make_float2(Fe.x - WFo.x, -(Fe.y - WFo.y));
            float2 Kk = K1[idx], Kj = K2[idx];
            float2 Yk = cmul(Xk, Kk), Yj = cmul(Xj, Kj);
            float2 Ge = make_float2(0.5f * (Yk.x + Yj.x), 0.5f * (Yk.y - Yj.y));
            float2 Gd = make_float2(0.5f * (Yk.x - Yj.x), 0.5f * (Yk.y + Yj.y));
            float2 Go = make_float2(c * Gd.x + s * Gd.y, c * Gd.y - s * Gd.x);
            Z[ra] = make_float2(Ge.x - Go.y, Ge.y + Go.x);
            Z[rb] = make_float2(Ge.x + Go.y, Go.x - Ge.y);
        }
    }
    __syncthreads();

    fft_inv_8k(Z);                        // leaves plain layout, synced

    // final inverse stage m=4096 fused with store (first half only), plain layout
    float bv = bias[d];
    const float scl = 1.0f / (float)N2;
#pragma unroll
    for (int it = 0; it < 8; it++) {
        int i = tid + it * NT;
        float2 w = __ldg(&g_tw[i]);
        float2 zb = Z[i + 4096];
        float tx = zb.x * w.x + zb.y * w.y;
        float ty = zb.y * w.x - zb.x * w.y;
        float2 za = Z[i];
        xrow[i] = make_float2(fmaf(za.x + tx, scl, bv), fmaf(za.y + ty, scl, bv));
    }
}

// ============================================================================
// launch — transpose_in forked onto a second stream so it overlaps the
// filter chain (twfill -> mlp -> kgemm -> kfft). Captured fork/join via events.
// ============================================================================
extern "C" void kernel_launch(void* const* d_in, const int* in_sizes, int n_in,
                              void* d_out, int out_size) {
    (void)in_sizes; (void)n_in; (void)out_size;
    const float* x       = (const float*)d_in[0];
    const float* w_in    = (const float*)d_in[1];
    const float* b_in    = (const float*)d_in[2];
    const float* freq_in = (const float*)d_in[3];
    const float* w_h0    = (const float*)d_in[4];
    const float* b_h0    = (const float*)d_in[5];
    const float* freq_h0 = (const float*)d_in[6];
    const float* w_h1    = (const float*)d_in[7];
    const float* b_h1    = (const float*)d_in[8];
    const float* freq_h1 = (const float*)d_in[9];
    const float* w_out   = (const float*)d_in[10];
    const float* bias    = (const float*)d_in[11];
    float* out = (float*)d_out;

    const int smemBytes = 8192 * sizeof(float2);   // 64 KB (Z only)
    cudaFuncSetAttribute(kfft_kernel,    cudaFuncAttributeMaxDynamicSharedMemorySize, smemBytes);
    cudaFuncSetAttribute(fftconv_kernel, cudaFuncAttributeMaxDynamicSharedMemorySize, smemBytes);

    cudaStream_t s2;
    cudaEvent_t evFork, evJoin;
    cudaStreamCreateWithFlags(&s2, cudaStreamNonBlocking);
    cudaEventCreateWithFlags(&evFork, cudaEventDisableTiming);
    cudaEventCreateWithFlags(&evJoin, cudaEventDisableTiming);

    // fork: transpose_in on s2
    cudaEventRecord(evFork, 0);
    cudaStreamWaitEvent(s2, evFork, 0);
    transpose_in<<<dim3(SEQLEN / 32, HD / 32, NB), dim3(32, 8), 0, s2>>>(x);
    cudaEventRecord(evJoin, s2);

    // filter chain on the main (capture) stream
    twfill_kernel<<<32, 256>>>();
    mlp_kernel<<<SEQLEN, FO>>>(w_in, b_in, freq_in, w_h0, b_h0, freq_h0, w_h1, b_h1, freq_h1);
    kgemm_kernel<<<dim3(SEQLEN / 128, HD / 32), 256>>>(w_out);
    kfft_kernel<<<HD, NT, smemBytes>>>();

    // join, then convolution + output transpose
    cudaStreamWaitEvent(0, evJoin, 0);
    fftconv_kernel<<<NB * HD, NT, smemBytes>>>(bias);
    transpose_out<<<dim3(SEQLEN / 32, HD / 32, NB), dim3(32, 8)>>>(out);

    cudaEventDestroy(evFork);
    cudaEventDestroy(evJoin);
    cudaStreamDestroy(s2);
}